// round 10
// baseline (speedup 1.0000x reference)
#include <cuda_runtime.h>
#include <math.h>
#include <stdint.h>

#define BB    64
#define SS    96
#define EE    300
#define DD    512
#define HH    256
#define MLPD  1024
#define FIVEH 1280
#define ROWS  191     // 96 leaves + 95 merge rows; root = row 190
#define NCTA  128
#define CL    16      // cluster size; 8 clusters x 8 batches

__device__ float g_states[BB * ROWS * DD];
__device__ float g_P[BB * ROWS * 256];       // selector projections [L(128)|R(128)]
__device__ float g_a2[2][BB * FIVEH];        // compose partials per K-half
__device__ float g_x1[BB * MLPD];
__device__ float g_x2[BB * MLPD];

#define CLUSTER_SYNC() do { \
    asm volatile("barrier.cluster.arrive.aligned;" ::: "memory"); \
    asm volatile("barrier.cluster.wait.aligned;" ::: "memory"); \
} while (0)

__device__ __forceinline__ float fsigm(float x) {
    return __fdividef(1.0f, 1.0f + __expf(-x));
}
__device__ __forceinline__ float ftanh(float x) {
    float cx = fminf(fmaxf(x, -15.0f), 15.0f);
    float e = __expf(2.0f * cx);
    return __fdividef(e - 1.0f, e + 1.0f);
}

// pair logit: full-warp; result valid on lane 0.
__device__ __forceinline__ float pair_logit(int b, int ra, int rb,
    const float* __restrict__ b1, const float* __restrict__ w2, int lane)
{
    int u = lane * 4;
    float4 pl = __ldcg((const float4*)&g_P[((size_t)b * ROWS + ra) * 256 + u]);
    float4 pr = __ldcg((const float4*)&g_P[((size_t)b * ROWS + rb) * 256 + 128 + u]);
    float4 bb = *(const float4*)&b1[u];
    float4 ww = *(const float4*)&w2[u];
    float s = ftanh(pl.x + pr.x + bb.x) * ww.x + ftanh(pl.y + pr.y + bb.y) * ww.y
            + ftanh(pl.z + pr.z + bb.z) * ww.z + ftanh(pl.w + pr.w + bb.w) * ww.w;
    for (int o = 16; o; o >>= 1) s += __shfl_down_sync(0xFFFFFFFFu, s, o);
    return s;
}

// ---------------------------------------------------------------------------
// encode: states[b][s][:] = embed[sent[b,s]] @ W_enc + b_enc   (rows 0..95)
// ---------------------------------------------------------------------------
__global__ __launch_bounds__(256) void encode_kernel(
    const int* __restrict__ sent, const float* __restrict__ emb,
    const float* __restrict__ Wenc, const float* __restrict__ benc)
{
    __shared__ float As[64 * 20];
    __shared__ float Bs[20 * 64];
    __shared__ int words[64];
    const int cb = blockIdx.x, tb = blockIdx.y, tid = threadIdx.x;
    const int tokenbase = tb * 64, colbase = cb * 64;
    if (tid < 64) words[tid] = sent[tokenbase + tid];
    __syncthreads();
    const int tx = tid & 15, ty = tid >> 4;
    float acc[4][4];
#pragma unroll
    for (int i = 0; i < 4; i++)
#pragma unroll
        for (int j = 0; j < 4; j++) acc[i][j] = 0.0f;
    for (int kb = 0; kb < EE; kb += 20) {
#pragma unroll
        for (int i = 0; i < 5; i++) {
            int e = tid + 256 * i, r = e / 20, k = e % 20;
            As[e] = emb[(size_t)words[r] * EE + kb + k];
        }
#pragma unroll
        for (int i = 0; i < 5; i++) {
            int e = tid + 256 * i, k = e >> 6, c = e & 63;
            Bs[e] = Wenc[(size_t)(kb + k) * DD + colbase + c];
        }
        __syncthreads();
#pragma unroll
        for (int k = 0; k < 20; k++) {
            float a0 = As[(4 * ty + 0) * 20 + k], a1 = As[(4 * ty + 1) * 20 + k];
            float a2 = As[(4 * ty + 2) * 20 + k], a3 = As[(4 * ty + 3) * 20 + k];
            float b0 = Bs[k * 64 + 4 * tx + 0], b1 = Bs[k * 64 + 4 * tx + 1];
            float b2 = Bs[k * 64 + 4 * tx + 2], b3 = Bs[k * 64 + 4 * tx + 3];
            acc[0][0] += a0 * b0; acc[0][1] += a0 * b1; acc[0][2] += a0 * b2; acc[0][3] += a0 * b3;
            acc[1][0] += a1 * b0; acc[1][1] += a1 * b1; acc[1][2] += a1 * b2; acc[1][3] += a1 * b3;
            acc[2][0] += a2 * b0; acc[2][1] += a2 * b1; acc[2][2] += a2 * b2; acc[2][3] += a2 * b3;
            acc[3][0] += a3 * b0; acc[3][1] += a3 * b1; acc[3][2] += a3 * b2; acc[3][3] += a3 * b3;
        }
        __syncthreads();
    }
#pragma unroll
    for (int i = 0; i < 4; i++) {
        int tok = tokenbase + 4 * ty + i;
        int b = tok / SS, s = tok - b * SS;
        int col = colbase + 4 * tx;
        float4 bia = *(const float4*)(benc + col);
        float4 v;
        v.x = acc[i][0] + bia.x; v.y = acc[i][1] + bia.y;
        v.z = acc[i][2] + bia.z; v.w = acc[i][3] + bia.w;
        *(float4*)(g_states + ((size_t)b * ROWS + s) * DD + col) = v;
    }
}

// ---------------------------------------------------------------------------
// persistent scan: 8 clusters x 16 CTAs; cluster -> 8 batches.
// CTA rank r: cs = r&7 (160-col slice), hf = r>>3 (256-K half).
// W_comp slice (160x256 = 160KB) resident in SMEM for the whole kernel.
// ---------------------------------------------------------------------------
__global__ __launch_bounds__(256, 1) __cluster_dims__(CL, 1, 1)
void scan_kernel(
    const float* __restrict__ Wcomp, const float* __restrict__ bcomp,
    const float* __restrict__ Wsel1, const float* __restrict__ bsel1,
    const float* __restrict__ Wsel2, const float* __restrict__ bsel2,
    const float* __restrict__ Wm1, const float* __restrict__ bm1,
    const float* __restrict__ Wm2, const float* __restrict__ bm2,
    const float* __restrict__ Wout, const float* __restrict__ bout,
    float* __restrict__ out)
{
    extern __shared__ float sm[];
    float* s_w     = sm;                      // 40960 : W_comp slice [dd(256)][160]
    float* s_ws    = s_w + 40960;             // 4096  : Wsel1 slice [dd(256)][16]
    float* s_U     = s_ws + 4096;             // 5120  : union {x(2080) | part(5120)} ; s_h = U+2080
    float* s_logit = s_U + 5120;              // 1536  : 2 x 8 x 96 ping-pong
    int*   s_ord   = (int*)(s_logit + 1536);  // 1536
    int*   s_sL    = s_ord + 1536;            // 8
    int*   s_sR    = s_sL + 8;                // 8

    const int tid  = threadIdx.x;
    const int r    = blockIdx.x & (CL - 1);
    const int b0   = (blockIdx.x >> 4) * 8;
    const int lane = tid & 31;
    const int wid  = tid >> 5;                 // warp = batch for warp-tasks
    const int cs   = r & 7;                    // col slice
    const int hf   = r >> 3;                   // K half (also lr for P slice)
    const int u0   = (r & 7) * 16;             // Wsel1 col base for this CTA's 16 kP
    const float b2v = bsel2[0];

    // ---- load Wsel1 slice: rows hf*256+dd, cols u0..u0+15 ----
    for (int i = tid; i < 4096; i += 256) {
        int dd = i >> 4, kl = i & 15;
        s_ws[i] = Wsel1[(size_t)(hf * 256 + dd) * 128 + u0 + kl];
    }

    // ---- P-init: leaf rows 0..95, 16 rows per pass, h staged through s_w ----
    for (int s0 = 0; s0 < SS; s0 += 16) {
        for (int i = tid; i < 8192; i += 256) {           // f4: 8 b x 16 rows x 64
            int m = i >> 10, rem = i & 1023, rr = rem >> 6, dq = rem & 63;
            *(float4*)&s_w[(m * 16 + rr) * 256 + dq * 4] =
                __ldcg((const float4*)&g_states[((size_t)(b0 + m) * ROWS + s0 + rr) * DD + HH + dq * 4]);
        }
        __syncthreads();
        {
            const int kl = lane & 15, dh = lane >> 4;
            for (int rr = 0; rr < 16; rr++) {
                const float* hb = s_w + (wid * 16 + rr) * 256 + dh * 128;
                float acc = 0.0f;
#pragma unroll 8
                for (int d = 0; d < 128; d++) acc += hb[d] * s_ws[(dh * 128 + d) * 16 + kl];
                acc += __shfl_xor_sync(0xFFFFFFFFu, acc, 16);
                if (dh == 0)
                    g_P[((size_t)(b0 + wid) * ROWS + s0 + rr) * 256 + r * 16 + kl] = acc;
            }
        }
        __syncthreads();
    }

    // ---- load persistent W_comp slice into s_w ----
    for (int i = tid; i < 10240; i += 256) {              // f4: 256 dd x 40
        int dd = i / 40, cq = i - dd * 40;
        *(float4*)&s_w[dd * 160 + cq * 4] =
            *(const float4*)&Wcomp[(size_t)(hf * 256 + dd) * FIVEH + cs * 160 + cq * 4];
    }
    CLUSTER_SYNC();

    // ---- initial logits + ord into buffer 0 ----
    for (int i = tid; i < 768; i += 256) s_ord[i] = i % SS;
    for (int i = tid; i < 8 * (SS - 1); i += 256) {
        int m = i / (SS - 1), j = i - m * (SS - 1);
        size_t pb = ((size_t)(b0 + m) * ROWS + j) * 256;
        float s = 0.0f;
#pragma unroll 4
        for (int u4 = 0; u4 < 32; u4++) {
            float4 pl = __ldcg((const float4*)&g_P[pb + u4 * 4]);
            float4 pr = __ldcg((const float4*)&g_P[pb + 256 + 128 + u4 * 4]);
            float4 bb = *(const float4*)&bsel1[u4 * 4];
            float4 ww = *(const float4*)&Wsel2[u4 * 4];
            s += ftanh(pl.x + pr.x + bb.x) * ww.x + ftanh(pl.y + pr.y + bb.y) * ww.y
               + ftanh(pl.z + pr.z + bb.z) * ww.z + ftanh(pl.w + pr.w + bb.w) * ww.w;
        }
        s_logit[m * SS + j] = s + b2v;
    }
    __syncthreads();

    int idxReg = -1;

    // ================= main loop =================
    for (int t = 0; t < SS - 1; t++) {
        const int npairs = SS - 1 - t;
        // ---- part 1: bookkeeping + argmax (warp wid -> batch wid) ----
        {
            const int m = wid, b = b0 + m;
            const int co = (t & 1) * 768 + m * SS;
            if (t > 0) {
                const int po = ((t - 1) & 1) * 768 + m * SS;
                const int idx = idxReg;
                const int limO = SS - t - 1, limL = SS - t - 2;
                for (int j = lane; j <= limO; j += 32)
                    s_ord[co + j] = (j < idx) ? s_ord[po + j]
                                  : (j == idx ? SS + t - 1 : s_ord[po + j + 1]);
                for (int j = lane; j <= limL; j += 32)
                    s_logit[co + j] = (j < idx - 1) ? s_logit[po + j]
                                    : ((j > idx) ? s_logit[po + j + 1] : -1e30f);
                __syncwarp();
#pragma unroll
                for (int pi = 0; pi < 2; pi++) {
                    int p = idx - 1 + pi;
                    if (p >= 0 && p <= limL) {
                        float s = pair_logit(b, s_ord[co + p], s_ord[co + p + 1], bsel1, Wsel2, lane);
                        if (lane == 0) s_logit[co + p] = s + b2v;
                    }
                    __syncwarp();
                }
            }
            float bv = -1e30f; int bi = 1 << 30;
            for (int j = lane; j < npairs; j += 32) {
                float v = s_logit[co + j];
                if (v > bv) { bv = v; bi = j; }
            }
            for (int o = 16; o; o >>= 1) {
                float ov = __shfl_down_sync(0xFFFFFFFFu, bv, o);
                int   oi = __shfl_down_sync(0xFFFFFFFFu, bi, o);
                if (ov > bv || (ov == bv && oi < bi)) { bv = ov; bi = oi; }
            }
            idxReg = __shfl_sync(0xFFFFFFFFu, bi, 0);
            if (lane == 0) {
                s_sL[m] = s_ord[co + idxReg];
                s_sR[m] = s_ord[co + idxReg + 1];
            }
        }
        __syncthreads();

        // ---- stage x K-half: hf==0 -> hL, hf==1 -> hR ----
        for (int i = tid; i < 512; i += 256) {
            int m = i >> 6, dq = i & 63;
            int slot = hf ? s_sR[m] : s_sL[m];
            *(float4*)&s_U[m * 260 + dq * 4] =
                __ldcg((const float4*)&g_states[((size_t)(b0 + m) * ROWS + slot) * DD + HH + dq * 4]);
        }
        __syncthreads();

        // ---- compose GEMM slice: all-SMEM. warp: wb=batch group, wk=64-d slice ----
        {
            const int wb = wid >> 2, wk = wid & 3;
            const int d0 = wk * 64;
            float ac[4][5];
#pragma unroll
            for (int m = 0; m < 4; m++)
#pragma unroll
                for (int j = 0; j < 5; j++) ac[m][j] = 0.0f;
            const float* xb = s_U + (wb * 4) * 260 + d0;
            const float* wp = s_w + d0 * 160 + lane;
#pragma unroll 4
            for (int d = 0; d < 64; d++) {
                float w0 = wp[0], w1 = wp[32], w2 = wp[64], w3 = wp[96], w4 = wp[128];
                float x0 = xb[d], x1 = xb[260 + d], x2 = xb[520 + d], x3 = xb[780 + d];
                ac[0][0] += x0 * w0; ac[0][1] += x0 * w1; ac[0][2] += x0 * w2; ac[0][3] += x0 * w3; ac[0][4] += x0 * w4;
                ac[1][0] += x1 * w0; ac[1][1] += x1 * w1; ac[1][2] += x1 * w2; ac[1][3] += x1 * w3; ac[1][4] += x1 * w4;
                ac[2][0] += x2 * w0; ac[2][1] += x2 * w1; ac[2][2] += x2 * w2; ac[2][3] += x2 * w3; ac[2][4] += x2 * w4;
                ac[3][0] += x3 * w0; ac[3][1] += x3 * w1; ac[3][2] += x3 * w2; ac[3][3] += x3 * w3; ac[3][4] += x3 * w4;
                wp += 160;
            }
            __syncthreads();   // all x reads done; s_U becomes partial buffer
#pragma unroll
            for (int m = 0; m < 4; m++)
#pragma unroll
                for (int j = 0; j < 5; j++)
                    s_U[(wk * 8 + wb * 4 + m) * 160 + j * 32 + lane] = ac[m][j];
        }
        __syncthreads();
        for (int i = tid; i < 1280; i += 256) {
            int m = i / 160, c = i - m * 160;
            float v = s_U[m * 160 + c] + s_U[(8 + m) * 160 + c]
                    + s_U[(16 + m) * 160 + c] + s_U[(24 + m) * 160 + c];
            g_a2[hf][(size_t)(b0 + m) * FIVEH + cs * 160 + c] = v;
        }
        CLUSTER_SYNC();

        // ---- gates: all CTAs compute h; rank 0 writes states row R ----
        const int R = SS + t;
        {
            const int u = tid;
            const float bi0 = bcomp[u], bf1 = bcomp[HH + u], bf2 = bcomp[2 * HH + u];
            const float bo3 = bcomp[3 * HH + u], bg4 = bcomp[4 * HH + u];
#pragma unroll 2
            for (int m = 0; m < 8; m++) {
                const int b = b0 + m;
                const float* a0p = &g_a2[0][(size_t)b * FIVEH + u];
                const float* a1p = &g_a2[1][(size_t)b * FIVEH + u];
                float iv = __ldcg(a0p) + __ldcg(a1p) + bi0;
                float fl = __ldcg(a0p + HH) + __ldcg(a1p + HH) + bf1;
                float fr = __ldcg(a0p + 2 * HH) + __ldcg(a1p + 2 * HH) + bf2;
                float ov = __ldcg(a0p + 3 * HH) + __ldcg(a1p + 3 * HH) + bo3;
                float gc = __ldcg(a0p + 4 * HH) + __ldcg(a1p + 4 * HH) + bg4;
                size_t rb = (size_t)b * ROWS;
                float lc = __ldcg(&g_states[(rb + s_sL[m]) * DD + u]);
                float rc = __ldcg(&g_states[(rb + s_sR[m]) * DD + u]);
                float c = fsigm(fl) * lc + fsigm(fr) * rc + fsigm(iv) * ftanh(gc);
                float h = fsigm(ov) * ftanh(c);
                s_U[2080 + m * 260 + u] = h;
                if (r == 0) {
                    g_states[(rb + R) * DD + u] = c;
                    g_states[(rb + R) * DD + HH + u] = h;
                }
            }
        }
        __syncthreads();

        // ---- P projection for row R: warp=batch, 16 k x 2 d-halves, all SMEM ----
        {
            const int kl = lane & 15, dh = lane >> 4;
            const float* hb = s_U + 2080 + wid * 260 + dh * 128;
            float acc = 0.0f;
#pragma unroll 8
            for (int d = 0; d < 128; d++) acc += hb[d] * s_ws[(dh * 128 + d) * 16 + kl];
            acc += __shfl_xor_sync(0xFFFFFFFFu, acc, 16);
            if (dh == 0)
                g_P[((size_t)(b0 + wid) * ROWS + R) * 256 + r * 16 + kl] = acc;
        }
        CLUSTER_SYNC();
    }

    // ================= MLP (root = row 190) =================
    for (int i = tid; i < 512; i += 256) {     // stage h_root into s_h
        int m = i >> 6, dq = i & 63;
        *(float4*)&s_U[2080 + m * 260 + dq * 4] =
            __ldcg((const float4*)&g_states[((size_t)(b0 + m) * ROWS + 190) * DD + HH + dq * 4]);
    }
    __syncthreads();
    {   // layer 1: K=256 split over 8 warps (32 k each), 64 cols/CTA, 8 batches
        const int wk = wid;
        float a[8][2];
#pragma unroll
        for (int m = 0; m < 8; m++) { a[m][0] = 0.0f; a[m][1] = 0.0f; }
        const int col = r * 64 + lane;
#pragma unroll 2
        for (int k = wk * 32; k < wk * 32 + 32; k++) {
            float w0 = Wm1[(size_t)k * MLPD + col];
            float w1 = Wm1[(size_t)k * MLPD + col + 32];
#pragma unroll
            for (int m = 0; m < 8; m++) {
                float xv = s_U[2080 + m * 260 + k];
                a[m][0] += xv * w0; a[m][1] += xv * w1;
            }
        }
        __syncthreads();
#pragma unroll
        for (int m = 0; m < 8; m++) {
            s_U[(wk * 8 + m) * 64 + lane]      = a[m][0];
            s_U[(wk * 8 + m) * 64 + lane + 32] = a[m][1];
        }
        __syncthreads();
        for (int i = tid; i < 512; i += 256) {
            int m = i >> 6, c = i & 63;
            float v = 0.0f;
#pragma unroll
            for (int w = 0; w < 8; w++) v += s_U[(w * 8 + m) * 64 + c];
            int cg = r * 64 + c;
            g_x1[(size_t)(b0 + m) * MLPD + cg] = fmaxf(v + bm1[cg], 0.0f);
        }
    }
    CLUSTER_SYNC();
    for (int i = tid; i < 2048; i += 256) {    // stage x1 into s_w
        int m = i >> 8, kq = i & 255;
        *(float4*)&s_w[m * 1024 + kq * 4] = __ldcg((const float4*)&g_x1[(size_t)(b0 + m) * MLPD + kq * 4]);
    }
    __syncthreads();
    {   // layer 2: K=1024 split over 8 warps (128 k each), 64 cols/CTA, 8 batches
        const int wk = wid;
        float a[8][2];
#pragma unroll
        for (int m = 0; m < 8; m++) { a[m][0] = 0.0f; a[m][1] = 0.0f; }
        const int col = r * 64 + lane;
#pragma unroll 2
        for (int k = wk * 128; k < wk * 128 + 128; k++) {
            float w0 = Wm2[(size_t)k * MLPD + col];
            float w1 = Wm2[(size_t)k * MLPD + col + 32];
#pragma unroll
            for (int m = 0; m < 8; m++) {
                float xv = s_w[m * 1024 + k];
                a[m][0] += xv * w0; a[m][1] += xv * w1;
            }
        }
        __syncthreads();
#pragma unroll
        for (int m = 0; m < 8; m++) {
            s_U[(wk * 8 + m) * 64 + lane]      = a[m][0];
            s_U[(wk * 8 + m) * 64 + lane + 32] = a[m][1];
        }
        __syncthreads();
        for (int i = tid; i < 512; i += 256) {
            int m = i >> 6, c = i & 63;
            float v = 0.0f;
#pragma unroll
            for (int w = 0; w < 8; w++) v += s_U[(w * 8 + m) * 64 + c];
            int cg = r * 64 + c;
            g_x2[(size_t)(b0 + m) * MLPD + cg] = fmaxf(v + bm2[cg], 0.0f);
        }
    }
    CLUSTER_SYNC();
    if (r == 0) {   // layer 3: 8 batches x 3 outputs
        for (int i = tid; i < 2048; i += 256) {
            int m = i >> 8, kq = i & 255;
            *(float4*)&s_w[m * 1024 + kq * 4] = __ldcg((const float4*)&g_x2[(size_t)(b0 + m) * MLPD + kq * 4]);
        }
        __syncthreads();
        const int b = b0 + wid;
        const float* xb = s_w + wid * 1024;
        float a0 = 0, a1 = 0, a2 = 0;
        for (int k = lane; k < MLPD; k += 32) {
            float xv = xb[k];
            a0 += xv * Wout[k * 3 + 0];
            a1 += xv * Wout[k * 3 + 1];
            a2 += xv * Wout[k * 3 + 2];
        }
        for (int o = 16; o; o >>= 1) {
            a0 += __shfl_down_sync(0xFFFFFFFFu, a0, o);
            a1 += __shfl_down_sync(0xFFFFFFFFu, a1, o);
            a2 += __shfl_down_sync(0xFFFFFFFFu, a2, o);
        }
        if (lane == 0) {
            out[b * 3 + 0] = a0 + bout[0];
            out[b * 3 + 1] = a1 + bout[1];
            out[b * 3 + 2] = a2 + bout[2];
        }
    }
}

// ---------------------------------------------------------------------------
extern "C" void kernel_launch(void* const* d_in, const int* in_sizes, int n_in,
                              void* d_out, int out_size)
{
    const int*   sent  = (const int*)d_in[0];
    const float* emb   = (const float*)d_in[2];
    const float* Wenc  = (const float*)d_in[3];
    const float* benc  = (const float*)d_in[4];
    const float* Wcomp = (const float*)d_in[5];
    const float* bcomp = (const float*)d_in[6];
    const float* Wsel1 = (const float*)d_in[7];
    const float* bsel1 = (const float*)d_in[8];
    const float* Wsel2 = (const float*)d_in[9];
    const float* bsel2 = (const float*)d_in[10];
    const float* Wm1   = (const float*)d_in[11];
    const float* bm1   = (const float*)d_in[12];
    const float* Wm2   = (const float*)d_in[13];
    const float* bm2   = (const float*)d_in[14];
    const float* Wout  = (const float*)d_in[15];
    const float* bout  = (const float*)d_in[16];
    float* out = (float*)d_out;

    // floats: 40960 + 4096 + 5120 + 1536 = 51712 ; ints: 1536 + 16
    const int smem_scan = 51712 * 4 + 1552 * 4;   // 213,056 B
    cudaFuncSetAttribute(scan_kernel, cudaFuncAttributeMaxDynamicSharedMemorySize, smem_scan);
    cudaFuncSetAttribute(scan_kernel, cudaFuncAttributeNonPortableClusterSizeAllowed, 1);

    encode_kernel<<<dim3(8, 96), 256>>>(sent, emb, Wenc, benc);
    scan_kernel<<<NCTA, 256, smem_scan>>>(Wcomp, bcomp, Wsel1, bsel1, Wsel2, bsel2,
                                          Wm1, bm1, Wm2, bm2, Wout, bout, out);
}

// round 11
// speedup vs baseline: 1.0361x; 1.0361x over previous
#include <cuda_runtime.h>
#include <math.h>
#include <stdint.h>

#define BB    64
#define SS    96
#define EE    300
#define DD    512
#define HH    256
#define MLPD  1024
#define FIVEH 1280
#define ROWS  191     // 96 leaves + 95 merge rows; root = row 190
#define NCTA  128
#define CL    8       // cluster size; 16 clusters x 4 batches
#define NT    512     // threads per scan CTA (16 warps)

__device__ float g_states[BB * ROWS * DD];
__device__ float g_P[BB * ROWS * 256];     // selector projections [L(128)|R(128)]
__device__ float g_a[BB * FIVEH];
__device__ float g_x1[BB * MLPD];
__device__ float g_x2[BB * MLPD];

#define CLUSTER_SYNC() do { \
    asm volatile("barrier.cluster.arrive.aligned;" ::: "memory"); \
    asm volatile("barrier.cluster.wait.aligned;" ::: "memory"); \
} while (0)

__device__ __forceinline__ float fsigm(float x) {
    return __fdividef(1.0f, 1.0f + __expf(-x));
}
__device__ __forceinline__ float ftanh(float x) {
    float cx = fminf(fmaxf(x, -15.0f), 15.0f);
    float e = __expf(2.0f * cx);
    return __fdividef(e - 1.0f, e + 1.0f);
}

// pair logit: full-warp; result valid on lane 0.
__device__ __forceinline__ float pair_logit(int b, int ra, int rb,
    const float* __restrict__ b1, const float* __restrict__ w2, int lane)
{
    int u = lane * 4;
    float4 pl = __ldcg((const float4*)&g_P[((size_t)b * ROWS + ra) * 256 + u]);
    float4 pr = __ldcg((const float4*)&g_P[((size_t)b * ROWS + rb) * 256 + 128 + u]);
    float4 bb = *(const float4*)&b1[u];
    float4 ww = *(const float4*)&w2[u];
    float s = ftanh(pl.x + pr.x + bb.x) * ww.x + ftanh(pl.y + pr.y + bb.y) * ww.y
            + ftanh(pl.z + pr.z + bb.z) * ww.z + ftanh(pl.w + pr.w + bb.w) * ww.w;
    for (int o = 16; o; o >>= 1) s += __shfl_down_sync(0xFFFFFFFFu, s, o);
    return s;
}

// ---------------------------------------------------------------------------
// encode: states[b][s][:] = embed[sent[b,s]] @ W_enc + b_enc   (rows 0..95)
// ---------------------------------------------------------------------------
__global__ __launch_bounds__(256) void encode_kernel(
    const int* __restrict__ sent, const float* __restrict__ emb,
    const float* __restrict__ Wenc, const float* __restrict__ benc)
{
    __shared__ float As[64 * 20];
    __shared__ float Bs[20 * 64];
    __shared__ int words[64];
    const int cb = blockIdx.x, tb = blockIdx.y, tid = threadIdx.x;
    const int tokenbase = tb * 64, colbase = cb * 64;
    if (tid < 64) words[tid] = sent[tokenbase + tid];
    __syncthreads();
    const int tx = tid & 15, ty = tid >> 4;
    float acc[4][4];
#pragma unroll
    for (int i = 0; i < 4; i++)
#pragma unroll
        for (int j = 0; j < 4; j++) acc[i][j] = 0.0f;
    for (int kb = 0; kb < EE; kb += 20) {
#pragma unroll
        for (int i = 0; i < 5; i++) {
            int e = tid + 256 * i, r = e / 20, k = e % 20;
            As[e] = emb[(size_t)words[r] * EE + kb + k];
        }
#pragma unroll
        for (int i = 0; i < 5; i++) {
            int e = tid + 256 * i, k = e >> 6, c = e & 63;
            Bs[e] = Wenc[(size_t)(kb + k) * DD + colbase + c];
        }
        __syncthreads();
#pragma unroll
        for (int k = 0; k < 20; k++) {
            float a0 = As[(4 * ty + 0) * 20 + k], a1 = As[(4 * ty + 1) * 20 + k];
            float a2 = As[(4 * ty + 2) * 20 + k], a3 = As[(4 * ty + 3) * 20 + k];
            float b0 = Bs[k * 64 + 4 * tx + 0], b1 = Bs[k * 64 + 4 * tx + 1];
            float b2 = Bs[k * 64 + 4 * tx + 2], b3 = Bs[k * 64 + 4 * tx + 3];
            acc[0][0] += a0 * b0; acc[0][1] += a0 * b1; acc[0][2] += a0 * b2; acc[0][3] += a0 * b3;
            acc[1][0] += a1 * b0; acc[1][1] += a1 * b1; acc[1][2] += a1 * b2; acc[1][3] += a1 * b3;
            acc[2][0] += a2 * b0; acc[2][1] += a2 * b1; acc[2][2] += a2 * b2; acc[2][3] += a2 * b3;
            acc[3][0] += a3 * b0; acc[3][1] += a3 * b1; acc[3][2] += a3 * b2; acc[3][3] += a3 * b3;
        }
        __syncthreads();
    }
#pragma unroll
    for (int i = 0; i < 4; i++) {
        int tok = tokenbase + 4 * ty + i;
        int b = tok / SS, s = tok - b * SS;
        int col = colbase + 4 * tx;
        float4 bia = *(const float4*)(benc + col);
        float4 v;
        v.x = acc[i][0] + bia.x; v.y = acc[i][1] + bia.y;
        v.z = acc[i][2] + bia.z; v.w = acc[i][3] + bia.w;
        *(float4*)(g_states + ((size_t)b * ROWS + s) * DD + col) = v;
    }
}

// ---------------------------------------------------------------------------
// persistent scan: 16 clusters of 8 CTAs; cluster -> 4 batches; 512 thr/CTA.
// CTA rank r -> 160-col slice of compose outputs, 32-k slice of P.
// ---------------------------------------------------------------------------
__global__ __launch_bounds__(NT, 1) __cluster_dims__(CL, 1, 1)
void scan_kernel(
    const float* __restrict__ Wcomp, const float* __restrict__ bcomp,
    const float* __restrict__ Wsel1, const float* __restrict__ bsel1,
    const float* __restrict__ Wsel2, const float* __restrict__ bsel2,
    const float* __restrict__ Wm1, const float* __restrict__ bm1,
    const float* __restrict__ Wm2, const float* __restrict__ bm2,
    const float* __restrict__ Wout, const float* __restrict__ bout,
    float* __restrict__ out)
{
    extern __shared__ float sm[];
    float* s_x     = sm;                     // 4*1040 = 4160
    float* s_h     = s_x + 4160;             // 4*260  = 1040
    float* s_part  = s_h + 1040;             // 16*4*160 = 10240
    float* s_logit = s_part + 10240;         // 2*4*96 = 768 (ping-pong)
    int*   s_ord   = (int*)(s_logit + 768);  // 768
    int*   s_sL    = s_ord + 768;            // 4
    int*   s_sR    = s_sL + 4;               // 4

    const int tid  = threadIdx.x;
    const int r    = blockIdx.x & (CL - 1);      // cluster rank
    const int b0   = (blockIdx.x >> 3) * 4;      // first batch of cluster
    const int lane = tid & 31;
    const int wid  = tid >> 5;                   // 16 warps
    const float b2v = bsel2[0];

    // P slice: kP = r*32 + lane
    const int kP  = r * 32 + lane;
    const int lrP = kP >> 7;
    const int uP  = kP & 127;
    const int wmm = wid & 3;                     // batch for warp-tasks
    const int wq  = wid >> 2;                    // d-quarter (0..3) for P tasks

    // ================= P-init: leaf rows 0..95, 4 rows per pass ================
    {
        const float* wcol = Wsel1 + (size_t)(lrP * 256 + wq * 64) * 128 + uP;
        for (int s0 = 0; s0 < SS; s0 += 4) {
            for (int i = tid; i < 1024; i += NT) {
                int m = i >> 8, rem = i & 255, rr = rem >> 6, dq = rem & 63;
                *(float4*)&s_x[m * 1040 + rr * 260 + dq * 4] =
                    __ldcg((const float4*)&g_states[((size_t)(b0 + m) * ROWS + s0 + rr) * DD + HH + dq * 4]);
            }
            __syncthreads();
#pragma unroll
            for (int rr = 0; rr < 4; rr++) {
                const float* hb = s_x + wmm * 1040 + rr * 260 + wq * 64;
                float acc = 0.0f;
#pragma unroll 8
                for (int d = 0; d < 64; d++) acc += hb[d] * wcol[(size_t)d * 128];
                s_part[(wmm * 4 + rr) * 128 + wq * 32 + lane] = acc;
            }
            __syncthreads();
            for (int i = tid; i < 512; i += NT) {
                int slot = i >> 5, l2 = i & 31;
                int m = slot >> 2, rr = slot & 3;
                float v = s_part[slot * 128 + l2] + s_part[slot * 128 + 32 + l2]
                        + s_part[slot * 128 + 64 + l2] + s_part[slot * 128 + 96 + l2];
                g_P[((size_t)(b0 + m) * ROWS + s0 + rr) * 256 + r * 32 + l2] = v;
            }
            __syncthreads();
        }
    }
    CLUSTER_SYNC();

    // ================= initial logits + ord (buffer 0) ========================
    for (int i = tid; i < 384; i += NT) s_ord[i] = i % SS;
    for (int i = tid; i < 4 * (SS - 1); i += NT) {
        int m = i / (SS - 1), j = i - m * (SS - 1);
        size_t pb = ((size_t)(b0 + m) * ROWS + j) * 256;
        float s = 0.0f;
#pragma unroll 4
        for (int u4 = 0; u4 < 32; u4++) {
            float4 pl = __ldcg((const float4*)&g_P[pb + u4 * 4]);
            float4 pr = __ldcg((const float4*)&g_P[pb + 256 + 128 + u4 * 4]);
            float4 bb = *(const float4*)&bsel1[u4 * 4];
            float4 ww = *(const float4*)&Wsel2[u4 * 4];
            s += ftanh(pl.x + pr.x + bb.x) * ww.x + ftanh(pl.y + pr.y + bb.y) * ww.y
               + ftanh(pl.z + pr.z + bb.z) * ww.z + ftanh(pl.w + pr.w + bb.w) * ww.w;
        }
        s_logit[m * SS + j] = s + b2v;
    }
    __syncthreads();

    int idxReg = -1;

    // ================= main loop =================
    for (int t = 0; t < SS - 1; t++) {
        const int npairs = SS - 1 - t;
        // ---- part 1: bookkeeping + argmax (warps 0-3, one batch each) ----
        if (wid < 4) {
            const int m = wid, b = b0 + m;
            const int co = (t & 1) * 384 + m * SS;
            if (t > 0) {
                const int po = ((t - 1) & 1) * 384 + m * SS;
                const int idx = idxReg;
                const int limO = SS - t - 1, limL = SS - t - 2;
                for (int j = lane; j <= limO; j += 32)
                    s_ord[co + j] = (j < idx) ? s_ord[po + j]
                                  : (j == idx ? SS + t - 1 : s_ord[po + j + 1]);
                for (int j = lane; j <= limL; j += 32)
                    s_logit[co + j] = (j < idx - 1) ? s_logit[po + j]
                                    : ((j > idx) ? s_logit[po + j + 1] : -1e30f);
                __syncwarp();
#pragma unroll
                for (int pi = 0; pi < 2; pi++) {
                    int p = idx - 1 + pi;
                    if (p >= 0 && p <= limL) {
                        float s = pair_logit(b, s_ord[co + p], s_ord[co + p + 1], bsel1, Wsel2, lane);
                        if (lane == 0) s_logit[co + p] = s + b2v;
                    }
                    __syncwarp();
                }
            }
            float bv = -1e30f; int bi = 1 << 30;
            for (int j = lane; j < npairs; j += 32) {
                float v = s_logit[co + j];
                if (v > bv) { bv = v; bi = j; }
            }
            for (int o = 16; o; o >>= 1) {
                float ov = __shfl_down_sync(0xFFFFFFFFu, bv, o);
                int   oi = __shfl_down_sync(0xFFFFFFFFu, bi, o);
                if (ov > bv || (ov == bv && oi < bi)) { bv = ov; bi = oi; }
            }
            idxReg = __shfl_sync(0xFFFFFFFFu, bi, 0);
            if (lane == 0) {
                s_sL[m] = s_ord[co + idxReg];
                s_sR[m] = s_ord[co + idxReg + 1];
            }
        }
        __syncthreads();

        // ---- stage x = [hL;hR] for 4 batches ----
        for (int i = tid; i < 512; i += NT) {
            int m = i >> 7, dq = i & 127;
            int slot = (dq < 64) ? s_sL[m] : s_sR[m];
            *(float4*)&s_x[m * 1040 + dq * 4] =
                __ldcg((const float4*)&g_states[((size_t)(b0 + m) * ROWS + slot) * DD + HH + (dq & 63) * 4]);
        }
        __syncthreads();

        // ---- compose GEMM slice: 16 warps = 16 K-slices of 32 ----
        {
            const int q = lane;              // col within 32-block
            const int d0 = wid * 32;
            const float* Wb = Wcomp + (size_t)d0 * FIVEH + r * 160 + q;
            float ac[4][5];
#pragma unroll
            for (int m = 0; m < 4; m++)
#pragma unroll
                for (int j = 0; j < 5; j++) ac[m][j] = 0.0f;
#pragma unroll 4
            for (int d = 0; d < 32; d++) {
                const float* wr = Wb + (size_t)d * FIVEH;
                float w0 = wr[0], w1 = wr[32], w2 = wr[64], w3 = wr[96], w4 = wr[128];
                float x0 = s_x[0 * 1040 + d0 + d];
                float x1 = s_x[1 * 1040 + d0 + d];
                float x2 = s_x[2 * 1040 + d0 + d];
                float x3 = s_x[3 * 1040 + d0 + d];
                ac[0][0] += x0 * w0; ac[0][1] += x0 * w1; ac[0][2] += x0 * w2; ac[0][3] += x0 * w3; ac[0][4] += x0 * w4;
                ac[1][0] += x1 * w0; ac[1][1] += x1 * w1; ac[1][2] += x1 * w2; ac[1][3] += x1 * w3; ac[1][4] += x1 * w4;
                ac[2][0] += x2 * w0; ac[2][1] += x2 * w1; ac[2][2] += x2 * w2; ac[2][3] += x2 * w3; ac[2][4] += x2 * w4;
                ac[3][0] += x3 * w0; ac[3][1] += x3 * w1; ac[3][2] += x3 * w2; ac[3][3] += x3 * w3; ac[3][4] += x3 * w4;
            }
#pragma unroll
            for (int m = 0; m < 4; m++)
#pragma unroll
                for (int j = 0; j < 5; j++)
                    s_part[(wid * 4 + m) * 160 + j * 32 + q] = ac[m][j];
        }
        __syncthreads();
        for (int i = tid; i < 640; i += NT) {
            int m = i / 160, c = i - m * 160;
            float v = bcomp[r * 160 + c];
#pragma unroll
            for (int ks = 0; ks < 16; ks++) v += s_part[(ks * 4 + m) * 160 + c];
            g_a[(b0 + m) * FIVEH + r * 160 + c] = v;
        }
        CLUSTER_SYNC();

        // ---- gates: all CTAs compute h (for P); rank 0 writes states row R ----
        const int R = SS + t;
        {
            const int u = tid & 255;
            const int g = tid >> 8;              // 0/1 -> batches {2g, 2g+1}
#pragma unroll
            for (int mm = 0; mm < 2; mm++) {
                const int m = g * 2 + mm;
                const int b = b0 + m;
                const float* ab = g_a + (size_t)b * FIVEH + u;
                float iv = __ldcg(ab), fl = __ldcg(ab + HH), fr = __ldcg(ab + 2 * HH);
                float ov = __ldcg(ab + 3 * HH), gc = __ldcg(ab + 4 * HH);
                size_t rb = (size_t)b * ROWS;
                float lc = __ldcg(&g_states[(rb + s_sL[m]) * DD + u]);
                float rc = __ldcg(&g_states[(rb + s_sR[m]) * DD + u]);
                float c = fsigm(fl) * lc + fsigm(fr) * rc + fsigm(iv) * ftanh(gc);
                float h = fsigm(ov) * ftanh(c);
                s_h[m * 260 + u] = h;
                if (r == 0) {
                    g_states[(rb + R) * DD + u] = c;
                    g_states[(rb + R) * DD + HH + u] = h;
                }
            }
        }
        __syncthreads();

        // ---- P projection for row R (16 warps: 4 batches x 4 d-quarters) ----
        {
            const float* wcol = Wsel1 + (size_t)(lrP * 256 + wq * 64) * 128 + uP;
            const float* hb = s_h + wmm * 260 + wq * 64;
            float acc = 0.0f;
#pragma unroll 8
            for (int d = 0; d < 64; d++) acc += hb[d] * wcol[(size_t)d * 128];
            s_part[wmm * 128 + wq * 32 + lane] = acc;
        }
        __syncthreads();
        for (int i = tid; i < 128; i += NT) {
            int m = i >> 5, l2 = i & 31;
            float v = s_part[m * 128 + l2] + s_part[m * 128 + 32 + l2]
                    + s_part[m * 128 + 64 + l2] + s_part[m * 128 + 96 + l2];
            g_P[((size_t)(b0 + m) * ROWS + R) * 256 + r * 32 + l2] = v;
        }
        CLUSTER_SYNC();
    }

    // ================= MLP (root = row 190) =================
    for (int i = tid; i < 1024; i += NT) {
        int m = i >> 8, d = i & 255;
        s_h[m * 260 + d] = __ldcg(&g_states[((size_t)(b0 + m) * ROWS + 190) * DD + HH + d]);
    }
    __syncthreads();
    {   // layer 1: per CTA 4 batches x 128 cols (of 1024), 1 col per thread
        const int m = tid >> 7, cc = tid & 127;
        const int col = r * 128 + cc;
        float a0 = 0;
        const float* hb = s_h + m * 260;
#pragma unroll 4
        for (int d = 0; d < 256; d++) a0 += hb[d] * Wm1[(size_t)d * MLPD + col];
        g_x1[(b0 + m) * MLPD + col] = fmaxf(a0 + bm1[col], 0.0f);
    }
    CLUSTER_SYNC();
    for (int i = tid; i < 1024; i += NT) {
        int m = i >> 8, k4 = i & 255;
        *(float4*)&s_x[m * 1040 + k4 * 4] = __ldcg((const float4*)&g_x1[(b0 + m) * MLPD + k4 * 4]);
    }
    __syncthreads();
    {   // layer 2: per CTA 4 batches x 128 cols, K=1024
        const int m = tid >> 7, cc = tid & 127;
        const int col = r * 128 + cc;
        float a0 = 0;
        const float* xb = s_x + m * 1040;
#pragma unroll 4
        for (int k = 0; k < MLPD; k++) a0 += xb[k] * Wm2[(size_t)k * MLPD + col];
        g_x2[(b0 + m) * MLPD + col] = fmaxf(a0 + bm2[col], 0.0f);
    }
    CLUSTER_SYNC();
    if (r == 0) {   // layer 3: 4 batches x 3 outputs
        for (int i = tid; i < 1024; i += NT) {
            int m = i >> 8, k4 = i & 255;
            *(float4*)&s_x[m * 1040 + k4 * 4] = __ldcg((const float4*)&g_x2[(b0 + m) * MLPD + k4 * 4]);
        }
        __syncthreads();
        if (wid < 4) {
            const int b = b0 + wid;
            const float* xb = s_x + wid * 1040;
            float a0 = 0, a1 = 0, a2 = 0;
            for (int k = lane; k < MLPD; k += 32) {
                float xv = xb[k];
                a0 += xv * Wout[k * 3 + 0];
                a1 += xv * Wout[k * 3 + 1];
                a2 += xv * Wout[k * 3 + 2];
            }
            for (int o = 16; o; o >>= 1) {
                a0 += __shfl_down_sync(0xFFFFFFFFu, a0, o);
                a1 += __shfl_down_sync(0xFFFFFFFFu, a1, o);
                a2 += __shfl_down_sync(0xFFFFFFFFu, a2, o);
            }
            if (lane == 0) {
                out[b * 3 + 0] = a0 + bout[0];
                out[b * 3 + 1] = a1 + bout[1];
                out[b * 3 + 2] = a2 + bout[2];
            }
        }
    }
}

// ---------------------------------------------------------------------------
extern "C" void kernel_launch(void* const* d_in, const int* in_sizes, int n_in,
                              void* d_out, int out_size)
{
    const int*   sent  = (const int*)d_in[0];
    const float* emb   = (const float*)d_in[2];
    const float* Wenc  = (const float*)d_in[3];
    const float* benc  = (const float*)d_in[4];
    const float* Wcomp = (const float*)d_in[5];
    const float* bcomp = (const float*)d_in[6];
    const float* Wsel1 = (const float*)d_in[7];
    const float* bsel1 = (const float*)d_in[8];
    const float* Wsel2 = (const float*)d_in[9];
    const float* bsel2 = (const float*)d_in[10];
    const float* Wm1   = (const float*)d_in[11];
    const float* bm1   = (const float*)d_in[12];
    const float* Wm2   = (const float*)d_in[13];
    const float* bm2   = (const float*)d_in[14];
    const float* Wout  = (const float*)d_in[15];
    const float* bout  = (const float*)d_in[16];
    float* out = (float*)d_out;

    // floats: 4160 + 1040 + 10240 + 768 = 16208 ; ints: 768 + 8
    const int smem_scan = 16208 * 4 + 776 * 4;
    cudaFuncSetAttribute(scan_kernel, cudaFuncAttributeMaxDynamicSharedMemorySize, smem_scan);

    encode_kernel<<<dim3(8, 96), 256>>>(sent, emb, Wenc, benc);
    scan_kernel<<<NCTA, NT, smem_scan>>>(Wcomp, bcomp, Wsel1, bsel1, Wsel2, bsel2,
                                         Wm1, bm1, Wm2, bm2, Wout, bout, out);
}

// round 12
// speedup vs baseline: 1.3867x; 1.3384x over previous
#include <cuda_runtime.h>
#include <math.h>
#include <stdint.h>

#define BB    64
#define SS    96
#define EE    300
#define DD    512
#define HH    256
#define MLPD  1024
#define FIVEH 1280
#define ROWS  191     // 96 leaves + 95 merge rows; root = row 190
#define NCTA  128
#define CL    8       // cluster size; 16 clusters x 4 batches
#define NT    256

__device__ float g_states[BB * ROWS * DD];
__device__ float g_P[BB * ROWS * 256];     // selector projections [L(128)|R(128)]
__device__ float g_x1[BB * MLPD];
__device__ float g_x2[BB * MLPD];

#define CLUSTER_SYNC() do { \
    asm volatile("barrier.cluster.arrive.aligned;" ::: "memory"); \
    asm volatile("barrier.cluster.wait.aligned;" ::: "memory"); \
} while (0)

__device__ __forceinline__ float fsigm(float x) {
    return __fdividef(1.0f, 1.0f + __expf(-x));
}
__device__ __forceinline__ float ftanh(float x) {
    float cx = fminf(fmaxf(x, -15.0f), 15.0f);
    float e = __expf(2.0f * cx);
    return __fdividef(e - 1.0f, e + 1.0f);
}

// pair logit: full-warp; result valid on lane 0.
__device__ __forceinline__ float pair_logit(int b, int ra, int rb,
    const float* __restrict__ b1, const float* __restrict__ w2, int lane)
{
    int u = lane * 4;
    float4 pl = __ldcg((const float4*)&g_P[((size_t)b * ROWS + ra) * 256 + u]);
    float4 pr = __ldcg((const float4*)&g_P[((size_t)b * ROWS + rb) * 256 + 128 + u]);
    float4 bb = *(const float4*)&b1[u];
    float4 ww = *(const float4*)&w2[u];
    float s = ftanh(pl.x + pr.x + bb.x) * ww.x + ftanh(pl.y + pr.y + bb.y) * ww.y
            + ftanh(pl.z + pr.z + bb.z) * ww.z + ftanh(pl.w + pr.w + bb.w) * ww.w;
    for (int o = 16; o; o >>= 1) s += __shfl_down_sync(0xFFFFFFFFu, s, o);
    return s;
}

// ---------------------------------------------------------------------------
// encode: states[b][s][:] = embed[sent[b,s]] @ W_enc + b_enc   (rows 0..95)
// ---------------------------------------------------------------------------
__global__ __launch_bounds__(256) void encode_kernel(
    const int* __restrict__ sent, const float* __restrict__ emb,
    const float* __restrict__ Wenc, const float* __restrict__ benc)
{
    __shared__ float As[64 * 20];
    __shared__ float Bs[20 * 64];
    __shared__ int words[64];
    const int cb = blockIdx.x, tb = blockIdx.y, tid = threadIdx.x;
    const int tokenbase = tb * 64, colbase = cb * 64;
    if (tid < 64) words[tid] = sent[tokenbase + tid];
    __syncthreads();
    const int tx = tid & 15, ty = tid >> 4;
    float acc[4][4];
#pragma unroll
    for (int i = 0; i < 4; i++)
#pragma unroll
        for (int j = 0; j < 4; j++) acc[i][j] = 0.0f;
    for (int kb = 0; kb < EE; kb += 20) {
#pragma unroll
        for (int i = 0; i < 5; i++) {
            int e = tid + 256 * i, r = e / 20, k = e % 20;
            As[e] = emb[(size_t)words[r] * EE + kb + k];
        }
#pragma unroll
        for (int i = 0; i < 5; i++) {
            int e = tid + 256 * i, k = e >> 6, c = e & 63;
            Bs[e] = Wenc[(size_t)(kb + k) * DD + colbase + c];
        }
        __syncthreads();
#pragma unroll
        for (int k = 0; k < 20; k++) {
            float a0 = As[(4 * ty + 0) * 20 + k], a1 = As[(4 * ty + 1) * 20 + k];
            float a2 = As[(4 * ty + 2) * 20 + k], a3 = As[(4 * ty + 3) * 20 + k];
            float b0 = Bs[k * 64 + 4 * tx + 0], b1 = Bs[k * 64 + 4 * tx + 1];
            float b2 = Bs[k * 64 + 4 * tx + 2], b3 = Bs[k * 64 + 4 * tx + 3];
            acc[0][0] += a0 * b0; acc[0][1] += a0 * b1; acc[0][2] += a0 * b2; acc[0][3] += a0 * b3;
            acc[1][0] += a1 * b0; acc[1][1] += a1 * b1; acc[1][2] += a1 * b2; acc[1][3] += a1 * b3;
            acc[2][0] += a2 * b0; acc[2][1] += a2 * b1; acc[2][2] += a2 * b2; acc[2][3] += a2 * b3;
            acc[3][0] += a3 * b0; acc[3][1] += a3 * b1; acc[3][2] += a3 * b2; acc[3][3] += a3 * b3;
        }
        __syncthreads();
    }
#pragma unroll
    for (int i = 0; i < 4; i++) {
        int tok = tokenbase + 4 * ty + i;
        int b = tok / SS, s = tok - b * SS;
        int col = colbase + 4 * tx;
        float4 bia = *(const float4*)(benc + col);
        float4 v;
        v.x = acc[i][0] + bia.x; v.y = acc[i][1] + bia.y;
        v.z = acc[i][2] + bia.z; v.w = acc[i][3] + bia.w;
        *(float4*)(g_states + ((size_t)b * ROWS + s) * DD + col) = v;
    }
}

// ---------------------------------------------------------------------------
// persistent scan: 16 clusters of 8 CTAs; cluster -> 4 batches; 256 thr/CTA.
// CTA rank r computes ALL 5 gates for unit stripe [r*32, r*32+32) (permuted
// Wcomp cols) -> gates are CTA-local. States row R is the h-exchange medium.
// ---------------------------------------------------------------------------
__global__ __launch_bounds__(NT, 1) __cluster_dims__(CL, 1, 1)
void scan_kernel(
    const float* __restrict__ Wcomp, const float* __restrict__ bcomp,
    const float* __restrict__ Wsel1, const float* __restrict__ bsel1,
    const float* __restrict__ Wsel2, const float* __restrict__ bsel2,
    const float* __restrict__ Wm1, const float* __restrict__ bm1,
    const float* __restrict__ Wm2, const float* __restrict__ bm2,
    const float* __restrict__ Wout, const float* __restrict__ bout,
    float* __restrict__ out)
{
    extern __shared__ float sm[];
    float* s_x     = sm;                     // 4160 : x = [hL;hR] x 4 batches
    float* s_ws    = s_x + 4160;             // 8192 : Wsel1 slice [d(256)][k32(32)]
    float* s_part  = s_ws + 8192;            // 5120 : GEMM partials
    float* s_hf    = s_part + 5120;          // 1024 : full h row R, 4 batches
    float* s_logit = s_hf + 1024;            // 768  : ping-pong
    int*   s_ord   = (int*)(s_logit + 768);  // 768  : ping-pong
    int*   s_sL    = s_ord + 768;            // 4
    int*   s_sR    = s_sL + 4;               // 4

    const int tid  = threadIdx.x;
    const int r    = blockIdx.x & (CL - 1);      // cluster rank
    const int b0   = (blockIdx.x >> 3) * 4;      // first batch of cluster
    const int lane = tid & 31;
    const int wid  = tid >> 5;                   // 8 warps
    const float b2v = bsel2[0];

    // leaf P-init slice (kP = r*32 + lane) as in R8
    const int kP  = r * 32 + lane;
    const int lrP = kP >> 7;
    const int uP  = kP & 127;
    const int wmm = wid & 3;
    const int wdh = wid >> 2;

    // ---- load persistent Wsel1 slice for in-loop P proj:
    // s_ws[d*32 + k32] = Wsel1[((r>>2)*256 + d)*128 + (r&3)*32 + k32]
    for (int i = tid; i < 8192; i += NT) {
        int d = i >> 5, k32 = i & 31;
        s_ws[i] = Wsel1[(size_t)((r >> 2) * 256 + d) * 128 + (r & 3) * 32 + k32];
    }

    // ================= P-init: leaf rows 0..95, 4 rows per pass (R8) =========
    {
        const float* wcol = Wsel1 + (size_t)(lrP * 256 + wdh * 128) * 128 + uP;
        for (int s0 = 0; s0 < SS; s0 += 4) {
            for (int i = tid; i < 1024; i += NT) {
                int m = i >> 8, rem = i & 255, rr = rem >> 6, dq = rem & 63;
                *(float4*)&s_x[m * 1040 + rr * 260 + dq * 4] =
                    __ldcg((const float4*)&g_states[((size_t)(b0 + m) * ROWS + s0 + rr) * DD + HH + dq * 4]);
            }
            __syncthreads();
#pragma unroll
            for (int rr = 0; rr < 4; rr++) {
                const float* hb = s_x + wmm * 1040 + rr * 260 + wdh * 128;
                float acc = 0.0f;
#pragma unroll 8
                for (int d = 0; d < 128; d++) acc += hb[d] * wcol[(size_t)d * 128];
                s_part[(wmm * 4 + rr) * 64 + wdh * 32 + lane] = acc;
            }
            __syncthreads();
            for (int i = tid; i < 512; i += NT) {
                int slot = i >> 5, l2 = i & 31;
                int m = slot >> 2, rr = slot & 3;
                float v = s_part[slot * 64 + l2] + s_part[slot * 64 + 32 + l2];
                g_P[((size_t)(b0 + m) * ROWS + s0 + rr) * 256 + r * 32 + l2] = v;
            }
            __syncthreads();
        }
    }
    CLUSTER_SYNC();

    // ================= initial logits + ord (buffer 0) ========================
    for (int i = tid; i < 384; i += NT) s_ord[i] = i % SS;
    for (int i = tid; i < 4 * (SS - 1); i += NT) {
        int m = i / (SS - 1), j = i - m * (SS - 1);
        size_t pb = ((size_t)(b0 + m) * ROWS + j) * 256;
        float s = 0.0f;
#pragma unroll 4
        for (int u4 = 0; u4 < 32; u4++) {
            float4 pl = __ldcg((const float4*)&g_P[pb + u4 * 4]);
            float4 pr = __ldcg((const float4*)&g_P[pb + 256 + 128 + u4 * 4]);
            float4 bb = *(const float4*)&bsel1[u4 * 4];
            float4 ww = *(const float4*)&Wsel2[u4 * 4];
            s += ftanh(pl.x + pr.x + bb.x) * ww.x + ftanh(pl.y + pr.y + bb.y) * ww.y
               + ftanh(pl.z + pr.z + bb.z) * ww.z + ftanh(pl.w + pr.w + bb.w) * ww.w;
        }
        s_logit[m * SS + j] = s + b2v;
    }
    __syncthreads();

    int idxReg = -1;

    // ================= main loop =================
    for (int t = 0; t < SS - 1; t++) {
        const int npairs = SS - 1 - t;
        // ---- part 1: bookkeeping + argmax (warps 0-3, one batch each) ----
        if (wid < 4) {
            const int m = wid, b = b0 + m;
            const int co = (t & 1) * 384 + m * SS;
            if (t > 0) {
                const int po = ((t - 1) & 1) * 384 + m * SS;
                const int idx = idxReg;
                const int limO = SS - t - 1, limL = SS - t - 2;
                for (int j = lane; j <= limO; j += 32)
                    s_ord[co + j] = (j < idx) ? s_ord[po + j]
                                  : (j == idx ? SS + t - 1 : s_ord[po + j + 1]);
                for (int j = lane; j <= limL; j += 32)
                    s_logit[co + j] = (j < idx - 1) ? s_logit[po + j]
                                    : ((j > idx) ? s_logit[po + j + 1] : -1e30f);
                __syncwarp();
#pragma unroll
                for (int pi = 0; pi < 2; pi++) {
                    int p = idx - 1 + pi;
                    if (p >= 0 && p <= limL) {
                        float s = pair_logit(b, s_ord[co + p], s_ord[co + p + 1], bsel1, Wsel2, lane);
                        if (lane == 0) s_logit[co + p] = s + b2v;
                    }
                    __syncwarp();
                }
            }
            float bv = -1e30f; int bi = 1 << 30;
            for (int j = lane; j < npairs; j += 32) {
                float v = s_logit[co + j];
                if (v > bv) { bv = v; bi = j; }
            }
            for (int o = 16; o; o >>= 1) {
                float ov = __shfl_down_sync(0xFFFFFFFFu, bv, o);
                int   oi = __shfl_down_sync(0xFFFFFFFFu, bi, o);
                if (ov > bv || (ov == bv && oi < bi)) { bv = ov; bi = oi; }
            }
            idxReg = __shfl_sync(0xFFFFFFFFu, bi, 0);
            if (lane == 0) {
                s_sL[m] = s_ord[co + idxReg];
                s_sR[m] = s_ord[co + idxReg + 1];
            }
        }
        __syncthreads();

        // ---- stage x = [hL;hR] for 4 batches ----
        for (int i = tid; i < 512; i += NT) {
            int m = i >> 7, dq = i & 127;
            int slot = (dq < 64) ? s_sL[m] : s_sR[m];
            *(float4*)&s_x[m * 1040 + dq * 4] =
                __ldcg((const float4*)&g_states[((size_t)(b0 + m) * ROWS + slot) * DD + HH + (dq & 63) * 4]);
        }
        __syncthreads();

        // ---- compose GEMM, PERMUTED cols: CTA r -> {g*256 + r*32 + lane} ----
        {
            const int d0 = wid * 64;
            const float* Wb = Wcomp + (size_t)d0 * FIVEH + r * 32 + lane;
            float ac[4][5];
#pragma unroll
            for (int m = 0; m < 4; m++)
#pragma unroll
                for (int j = 0; j < 5; j++) ac[m][j] = 0.0f;
#pragma unroll 2
            for (int d = 0; d < 64; d++) {
                const float* wr = Wb + (size_t)d * FIVEH;
                float w0 = wr[0], w1 = wr[256], w2 = wr[512], w3 = wr[768], w4 = wr[1024];
                float x0 = s_x[0 * 1040 + d0 + d];
                float x1 = s_x[1 * 1040 + d0 + d];
                float x2 = s_x[2 * 1040 + d0 + d];
                float x3 = s_x[3 * 1040 + d0 + d];
                ac[0][0] += x0 * w0; ac[0][1] += x0 * w1; ac[0][2] += x0 * w2; ac[0][3] += x0 * w3; ac[0][4] += x0 * w4;
                ac[1][0] += x1 * w0; ac[1][1] += x1 * w1; ac[1][2] += x1 * w2; ac[1][3] += x1 * w3; ac[1][4] += x1 * w4;
                ac[2][0] += x2 * w0; ac[2][1] += x2 * w1; ac[2][2] += x2 * w2; ac[2][3] += x2 * w3; ac[2][4] += x2 * w4;
                ac[3][0] += x3 * w0; ac[3][1] += x3 * w1; ac[3][2] += x3 * w2; ac[3][3] += x3 * w3; ac[3][4] += x3 * w4;
            }
#pragma unroll
            for (int m = 0; m < 4; m++)
#pragma unroll
                for (int j = 0; j < 5; j++)
                    s_part[(wid * 4 + m) * 160 + j * 32 + lane] = ac[m][j];
        }
        __syncthreads();

        // ---- combine + gates (CTA-local!): tid<128 -> (m, u32) ----
        const int R = SS + t;
        if (tid < 128) {
            const int m = tid >> 5, u32 = tid & 31;
            const int u = r * 32 + u32;
            float val[5];
#pragma unroll
            for (int g = 0; g < 5; g++) {
                float s = bcomp[g * 256 + u];
#pragma unroll
                for (int ks = 0; ks < 8; ks++)
                    s += s_part[(ks * 4 + m) * 160 + g * 32 + u32];
                val[g] = s;
            }
            const int b = b0 + m;
            size_t rb = (size_t)b * ROWS;
            float lc = __ldcg(&g_states[(rb + s_sL[m]) * DD + u]);
            float rc = __ldcg(&g_states[(rb + s_sR[m]) * DD + u]);
            float c = fsigm(val[1]) * lc + fsigm(val[2]) * rc + fsigm(val[0]) * ftanh(val[4]);
            float h = fsigm(val[3]) * ftanh(c);
            g_states[(rb + R) * DD + u] = c;
            g_states[(rb + R) * DD + HH + u] = h;
        }
        CLUSTER_SYNC();   // row R (c,h) complete cluster-wide

        // ---- stage full h row R, then P proj (all smem weights) ----
        for (int i = tid; i < 256; i += NT) {
            int m = i >> 6, dq = i & 63;
            *(float4*)&s_hf[m * 256 + dq * 4] =
                __ldcg((const float4*)&g_states[((size_t)(b0 + m) * ROWS + R) * DD + HH + dq * 4]);
        }
        __syncthreads();
        if (tid < 128) {
            const int k32 = tid & 31, m = tid >> 5;
            const float* hb = s_hf + m * 256;
            float acc = 0.0f;
#pragma unroll 8
            for (int d = 0; d < 256; d++) acc += hb[d] * s_ws[d * 32 + k32];
            g_P[((size_t)(b0 + m) * ROWS + R) * 256 + r * 32 + k32] = acc;
        }
        CLUSTER_SYNC();
    }

    // ================= MLP (root = row 190) =================
    for (int i = tid; i < 256; i += NT) {
        int m = i >> 6, dq = i & 63;
        *(float4*)&s_hf[m * 256 + dq * 4] =
            __ldcg((const float4*)&g_states[((size_t)(b0 + m) * ROWS + 190) * DD + HH + dq * 4]);
    }
    __syncthreads();
    {   // layer 1: per CTA 4 batches x 128 cols (of 1024)
        const int m = tid >> 6, cc = tid & 63;
        const int col = r * 128 + cc;
        float a0 = 0, a1 = 0;
        const float* hb = s_hf + m * 256;
#pragma unroll 4
        for (int d = 0; d < 256; d++) {
            float hv = hb[d];
            a0 += hv * Wm1[(size_t)d * MLPD + col];
            a1 += hv * Wm1[(size_t)d * MLPD + col + 64];
        }
        g_x1[(b0 + m) * MLPD + col]      = fmaxf(a0 + bm1[col], 0.0f);
        g_x1[(b0 + m) * MLPD + col + 64] = fmaxf(a1 + bm1[col + 64], 0.0f);
    }
    CLUSTER_SYNC();
    for (int i = tid; i < 1024; i += NT) {
        int m = i >> 8, k4 = i & 255;
        *(float4*)&s_x[m * 1040 + k4 * 4] = __ldcg((const float4*)&g_x1[(b0 + m) * MLPD + k4 * 4]);
    }
    __syncthreads();
    {   // layer 2: per CTA 4 batches x 128 cols, K=1024
        const int m = tid >> 6, cc = tid & 63;
        const int col = r * 128 + cc;
        float a0 = 0, a1 = 0;
        const float* xb = s_x + m * 1040;
#pragma unroll 4
        for (int k = 0; k < MLPD; k++) {
            float xv = xb[k];
            a0 += xv * Wm2[(size_t)k * MLPD + col];
            a1 += xv * Wm2[(size_t)k * MLPD + col + 64];
        }
        g_x2[(b0 + m) * MLPD + col]      = fmaxf(a0 + bm2[col], 0.0f);
        g_x2[(b0 + m) * MLPD + col + 64] = fmaxf(a1 + bm2[col + 64], 0.0f);
    }
    CLUSTER_SYNC();
    if (r == 0) {   // layer 3: 4 batches x 3 outputs
        for (int i = tid; i < 1024; i += NT) {
            int m = i >> 8, k4 = i & 255;
            *(float4*)&s_x[m * 1040 + k4 * 4] = __ldcg((const float4*)&g_x2[(b0 + m) * MLPD + k4 * 4]);
        }
        __syncthreads();
        if (wid < 4) {
            const int b = b0 + wid;
            const float* xb = s_x + wid * 1040;
            float a0 = 0, a1 = 0, a2 = 0;
            for (int k = lane; k < MLPD; k += 32) {
                float xv = xb[k];
                a0 += xv * Wout[k * 3 + 0];
                a1 += xv * Wout[k * 3 + 1];
                a2 += xv * Wout[k * 3 + 2];
            }
            for (int o = 16; o; o >>= 1) {
                a0 += __shfl_down_sync(0xFFFFFFFFu, a0, o);
                a1 += __shfl_down_sync(0xFFFFFFFFu, a1, o);
                a2 += __shfl_down_sync(0xFFFFFFFFu, a2, o);
            }
            if (lane == 0) {
                out[b * 3 + 0] = a0 + bout[0];
                out[b * 3 + 1] = a1 + bout[1];
                out[b * 3 + 2] = a2 + bout[2];
            }
        }
    }
}

// ---------------------------------------------------------------------------
extern "C" void kernel_launch(void* const* d_in, const int* in_sizes, int n_in,
                              void* d_out, int out_size)
{
    const int*   sent  = (const int*)d_in[0];
    const float* emb   = (const float*)d_in[2];
    const float* Wenc  = (const float*)d_in[3];
    const float* benc  = (const float*)d_in[4];
    const float* Wcomp = (const float*)d_in[5];
    const float* bcomp = (const float*)d_in[6];
    const float* Wsel1 = (const float*)d_in[7];
    const float* bsel1 = (const float*)d_in[8];
    const float* Wsel2 = (const float*)d_in[9];
    const float* bsel2 = (const float*)d_in[10];
    const float* Wm1   = (const float*)d_in[11];
    const float* bm1   = (const float*)d_in[12];
    const float* Wm2   = (const float*)d_in[13];
    const float* bm2   = (const float*)d_in[14];
    const float* Wout  = (const float*)d_in[15];
    const float* bout  = (const float*)d_in[16];
    float* out = (float*)d_out;

    // floats: 4160+8192+5120+1024+768 = 19264 ; ints: 768+8
    const int smem_scan = 19264 * 4 + 776 * 4;
    cudaFuncSetAttribute(scan_kernel, cudaFuncAttributeMaxDynamicSharedMemorySize, smem_scan);

    encode_kernel<<<dim3(8, 96), 256>>>(sent, emb, Wenc, benc);
    scan_kernel<<<NCTA, NT, smem_scan>>>(Wcomp, bcomp, Wsel1, bsel1, Wsel2, bsel2,
                                         Wm1, bm1, Wm2, bm2, Wout, bout, out);
}

// round 13
// speedup vs baseline: 1.5494x; 1.1174x over previous
#include <cuda_runtime.h>
#include <math.h>
#include <stdint.h>

#define BB    64
#define SS    96
#define EE    300
#define DD    512
#define HH    256
#define MLPD  1024
#define FIVEH 1280
#define ROWS  191     // 96 leaves + 95 merge rows; root = row 190
#define NCTA  128
#define CL    8       // cluster size; 16 clusters x 4 batches
#define NT    256

__device__ float g_states[BB * ROWS * DD];
__device__ float g_P[BB * ROWS * 256];     // selector projections [L(128)|R(128)]
__device__ float g_x1[BB * MLPD];
__device__ float g_x2[BB * MLPD];

#define CLUSTER_SYNC() do { \
    asm volatile("barrier.cluster.arrive.aligned;" ::: "memory"); \
    asm volatile("barrier.cluster.wait.aligned;" ::: "memory"); \
} while (0)

__device__ __forceinline__ float fsigm(float x) {
    return __fdividef(1.0f, 1.0f + __expf(-x));
}
__device__ __forceinline__ float ftanh(float x) {
    float cx = fminf(fmaxf(x, -15.0f), 15.0f);
    float e = __expf(2.0f * cx);
    return __fdividef(e - 1.0f, e + 1.0f);
}

// store float to the same smem offset in a peer CTA of the cluster
__device__ __forceinline__ void dsmem_st(uint32_t local_addr, int peer, float v) {
    uint32_t ra;
    asm volatile("mapa.shared::cluster.u32 %0, %1, %2;" : "=r"(ra) : "r"(local_addr), "r"(peer));
    asm volatile("st.shared::cluster.f32 [%0], %1;" :: "r"(ra), "f"(v) : "memory");
}

// pair logit over a HALF-warp (16 lanes, 8 units each); valid at hl==0.
__device__ __forceinline__ float pair_logit16(int b, int ra, int rb, int hl,
    const float* __restrict__ b1, const float* __restrict__ w2)
{
    int u = hl * 8;
    size_t pa = ((size_t)b * ROWS + ra) * 256 + u;
    size_t pc = ((size_t)b * ROWS + rb) * 256 + 128 + u;
    float4 a0 = __ldcg((const float4*)&g_P[pa]);
    float4 a1 = __ldcg((const float4*)&g_P[pa + 4]);
    float4 c0 = __ldcg((const float4*)&g_P[pc]);
    float4 c1 = __ldcg((const float4*)&g_P[pc + 4]);
    float4 b0 = *(const float4*)&b1[u];
    float4 b4 = *(const float4*)&b1[u + 4];
    float4 w0 = *(const float4*)&w2[u];
    float4 w4 = *(const float4*)&w2[u + 4];
    float s = ftanh(a0.x + c0.x + b0.x) * w0.x + ftanh(a0.y + c0.y + b0.y) * w0.y
            + ftanh(a0.z + c0.z + b0.z) * w0.z + ftanh(a0.w + c0.w + b0.w) * w0.w
            + ftanh(a1.x + c1.x + b4.x) * w4.x + ftanh(a1.y + c1.y + b4.y) * w4.y
            + ftanh(a1.z + c1.z + b4.z) * w4.z + ftanh(a1.w + c1.w + b4.w) * w4.w;
    for (int o = 8; o; o >>= 1) s += __shfl_down_sync(0xFFFFFFFFu, s, o, 16);
    return s;
}

// full-warp pair logit (used only for init path parity) — 4 units/lane
__device__ __forceinline__ float pair_logit(int b, int ra, int rb,
    const float* __restrict__ b1, const float* __restrict__ w2, int lane)
{
    int u = lane * 4;
    float4 pl = __ldcg((const float4*)&g_P[((size_t)b * ROWS + ra) * 256 + u]);
    float4 pr = __ldcg((const float4*)&g_P[((size_t)b * ROWS + rb) * 256 + 128 + u]);
    float4 bb = *(const float4*)&b1[u];
    float4 ww = *(const float4*)&w2[u];
    float s = ftanh(pl.x + pr.x + bb.x) * ww.x + ftanh(pl.y + pr.y + bb.y) * ww.y
            + ftanh(pl.z + pr.z + bb.z) * ww.z + ftanh(pl.w + pr.w + bb.w) * ww.w;
    for (int o = 16; o; o >>= 1) s += __shfl_down_sync(0xFFFFFFFFu, s, o);
    return s;
}

// ---------------------------------------------------------------------------
// encode: states[b][s][:] = embed[sent[b,s]] @ W_enc + b_enc   (rows 0..95)
// ---------------------------------------------------------------------------
__global__ __launch_bounds__(256) void encode_kernel(
    const int* __restrict__ sent, const float* __restrict__ emb,
    const float* __restrict__ Wenc, const float* __restrict__ benc)
{
    __shared__ float As[64 * 20];
    __shared__ float Bs[20 * 64];
    __shared__ int words[64];
    const int cb = blockIdx.x, tb = blockIdx.y, tid = threadIdx.x;
    const int tokenbase = tb * 64, colbase = cb * 64;
    if (tid < 64) words[tid] = sent[tokenbase + tid];
    __syncthreads();
    const int tx = tid & 15, ty = tid >> 4;
    float acc[4][4];
#pragma unroll
    for (int i = 0; i < 4; i++)
#pragma unroll
        for (int j = 0; j < 4; j++) acc[i][j] = 0.0f;
    for (int kb = 0; kb < EE; kb += 20) {
#pragma unroll
        for (int i = 0; i < 5; i++) {
            int e = tid + 256 * i, r = e / 20, k = e % 20;
            As[e] = emb[(size_t)words[r] * EE + kb + k];
        }
#pragma unroll
        for (int i = 0; i < 5; i++) {
            int e = tid + 256 * i, k = e >> 6, c = e & 63;
            Bs[e] = Wenc[(size_t)(kb + k) * DD + colbase + c];
        }
        __syncthreads();
#pragma unroll
        for (int k = 0; k < 20; k++) {
            float a0 = As[(4 * ty + 0) * 20 + k], a1 = As[(4 * ty + 1) * 20 + k];
            float a2 = As[(4 * ty + 2) * 20 + k], a3 = As[(4 * ty + 3) * 20 + k];
            float b0 = Bs[k * 64 + 4 * tx + 0], b1 = Bs[k * 64 + 4 * tx + 1];
            float b2 = Bs[k * 64 + 4 * tx + 2], b3 = Bs[k * 64 + 4 * tx + 3];
            acc[0][0] += a0 * b0; acc[0][1] += a0 * b1; acc[0][2] += a0 * b2; acc[0][3] += a0 * b3;
            acc[1][0] += a1 * b0; acc[1][1] += a1 * b1; acc[1][2] += a1 * b2; acc[1][3] += a1 * b3;
            acc[2][0] += a2 * b0; acc[2][1] += a2 * b1; acc[2][2] += a2 * b2; acc[2][3] += a2 * b3;
            acc[3][0] += a3 * b0; acc[3][1] += a3 * b1; acc[3][2] += a3 * b2; acc[3][3] += a3 * b3;
        }
        __syncthreads();
    }
#pragma unroll
    for (int i = 0; i < 4; i++) {
        int tok = tokenbase + 4 * ty + i;
        int b = tok / SS, s = tok - b * SS;
        int col = colbase + 4 * tx;
        float4 bia = *(const float4*)(benc + col);
        float4 v;
        v.x = acc[i][0] + bia.x; v.y = acc[i][1] + bia.y;
        v.z = acc[i][2] + bia.z; v.w = acc[i][3] + bia.w;
        *(float4*)(g_states + ((size_t)b * ROWS + s) * DD + col) = v;
    }
}

// ---------------------------------------------------------------------------
// persistent scan: 16 clusters of 8 CTAs; cluster -> 4 batches; 256 thr/CTA.
// CTA rank r computes ALL 5 gates for unit stripe [r*32, r*32+32) (permuted
// Wcomp cols); h exchanged via DSMEM broadcast into every CTA's s_hf.
// ---------------------------------------------------------------------------
__global__ __launch_bounds__(NT, 1) __cluster_dims__(CL, 1, 1)
void scan_kernel(
    const float* __restrict__ Wcomp, const float* __restrict__ bcomp,
    const float* __restrict__ Wsel1, const float* __restrict__ bsel1,
    const float* __restrict__ Wsel2, const float* __restrict__ bsel2,
    const float* __restrict__ Wm1, const float* __restrict__ bm1,
    const float* __restrict__ Wm2, const float* __restrict__ bm2,
    const float* __restrict__ Wout, const float* __restrict__ bout,
    float* __restrict__ out)
{
    extern __shared__ float sm[];
    float* s_x     = sm;                     // 4160 : x = [hL;hR] x 4 batches
    float* s_ws    = s_x + 4160;             // 8192 : Wsel1 slice [d(256)][k32(32)]
    float* s_part  = s_ws + 8192;            // 5120 : GEMM partials
    float* s_hf    = s_part + 5120;          // 1024 : full h row R, 4 batches
    float* s_logit = s_hf + 1024;            // 768  : ping-pong
    int*   s_ord   = (int*)(s_logit + 768);  // 768  : ping-pong
    int*   s_sL    = s_ord + 768;            // 4
    int*   s_sR    = s_sL + 4;               // 4

    const int tid  = threadIdx.x;
    const int r    = blockIdx.x & (CL - 1);      // cluster rank
    const int b0   = (blockIdx.x >> 3) * 4;      // first batch of cluster
    const int lane = tid & 31;
    const int wid  = tid >> 5;                   // 8 warps
    const float b2v = bsel2[0];

    // leaf P-init slice (kP = r*32 + lane)
    const int kP  = r * 32 + lane;
    const int lrP = kP >> 7;
    const int uP  = kP & 127;
    const int wmm = wid & 3;
    const int wdh = wid >> 2;

    // ---- persistent Wsel1 slice for in-loop P proj ----
    for (int i = tid; i < 8192; i += NT) {
        int d = i >> 5, k32 = i & 31;
        s_ws[i] = Wsel1[(size_t)((r >> 2) * 256 + d) * 128 + (r & 3) * 32 + k32];
    }

    // ================= P-init: leaf rows 0..95, 4 rows per pass ==============
    {
        const float* wcol = Wsel1 + (size_t)(lrP * 256 + wdh * 128) * 128 + uP;
        for (int s0 = 0; s0 < SS; s0 += 4) {
            for (int i = tid; i < 1024; i += NT) {
                int m = i >> 8, rem = i & 255, rr = rem >> 6, dq = rem & 63;
                *(float4*)&s_x[m * 1040 + rr * 260 + dq * 4] =
                    __ldcg((const float4*)&g_states[((size_t)(b0 + m) * ROWS + s0 + rr) * DD + HH + dq * 4]);
            }
            __syncthreads();
#pragma unroll
            for (int rr = 0; rr < 4; rr++) {
                const float* hb = s_x + wmm * 1040 + rr * 260 + wdh * 128;
                float acc = 0.0f;
#pragma unroll 8
                for (int d = 0; d < 128; d++) acc += hb[d] * wcol[(size_t)d * 128];
                s_part[(wmm * 4 + rr) * 64 + wdh * 32 + lane] = acc;
            }
            __syncthreads();
            for (int i = tid; i < 512; i += NT) {
                int slot = i >> 5, l2 = i & 31;
                int m = slot >> 2, rr = slot & 3;
                float v = s_part[slot * 64 + l2] + s_part[slot * 64 + 32 + l2];
                g_P[((size_t)(b0 + m) * ROWS + s0 + rr) * 256 + r * 32 + l2] = v;
            }
            __syncthreads();
        }
    }
    CLUSTER_SYNC();

    // ================= initial logits + ord (buffer 0) ========================
    for (int i = tid; i < 384; i += NT) s_ord[i] = i % SS;
    for (int i = tid; i < 4 * (SS - 1); i += NT) {
        int m = i / (SS - 1), j = i - m * (SS - 1);
        size_t pb = ((size_t)(b0 + m) * ROWS + j) * 256;
        float s = 0.0f;
#pragma unroll 4
        for (int u4 = 0; u4 < 32; u4++) {
            float4 pl = __ldcg((const float4*)&g_P[pb + u4 * 4]);
            float4 pr = __ldcg((const float4*)&g_P[pb + 256 + 128 + u4 * 4]);
            float4 bb = *(const float4*)&bsel1[u4 * 4];
            float4 ww = *(const float4*)&Wsel2[u4 * 4];
            s += ftanh(pl.x + pr.x + bb.x) * ww.x + ftanh(pl.y + pr.y + bb.y) * ww.y
               + ftanh(pl.z + pr.z + bb.z) * ww.z + ftanh(pl.w + pr.w + bb.w) * ww.w;
        }
        s_logit[m * SS + j] = s + b2v;
    }
    __syncthreads();

    int idxReg = -1;

    // ================= main loop =================
    for (int t = 0; t < SS - 1; t++) {
        const int npairs = SS - 1 - t;
        // ---- part 1: bookkeeping + dual-logit (parallel halves) + argmax ----
        if (wid < 4) {
            const int m = wid, b = b0 + m;
            const int co = (t & 1) * 384 + m * SS;
            if (t > 0) {
                const int po = ((t - 1) & 1) * 384 + m * SS;
                const int idx = idxReg;
                const int limO = SS - t - 1, limL = SS - t - 2;
                for (int j = lane; j <= limO; j += 32)
                    s_ord[co + j] = (j < idx) ? s_ord[po + j]
                                  : (j == idx ? SS + t - 1 : s_ord[po + j + 1]);
                for (int j = lane; j <= limL; j += 32)
                    s_logit[co + j] = (j < idx - 1) ? s_logit[po + j]
                                    : ((j > idx) ? s_logit[po + j + 1] : -1e30f);
                __syncwarp();
                {   // both affected logits in parallel: lanes<16 -> idx-1, >=16 -> idx
                    int p = (lane < 16) ? (idx - 1) : idx;
                    bool valid = (p >= 0) && (p <= limL);
                    int pc = min(max(p, 0), limL);
                    float s = pair_logit16(b, s_ord[co + pc], s_ord[co + pc + 1],
                                           lane & 15, bsel1, Wsel2);
                    if ((lane == 0 || lane == 16) && valid) s_logit[co + p] = s + b2v;
                }
                __syncwarp();
            }
            float bv = -1e30f; int bi = 1 << 30;
            for (int j = lane; j < npairs; j += 32) {
                float v = s_logit[co + j];
                if (v > bv) { bv = v; bi = j; }
            }
            for (int o = 16; o; o >>= 1) {
                float ov = __shfl_down_sync(0xFFFFFFFFu, bv, o);
                int   oi = __shfl_down_sync(0xFFFFFFFFu, bi, o);
                if (ov > bv || (ov == bv && oi < bi)) { bv = ov; bi = oi; }
            }
            idxReg = __shfl_sync(0xFFFFFFFFu, bi, 0);
            if (lane == 0) {
                s_sL[m] = s_ord[co + idxReg];
                s_sR[m] = s_ord[co + idxReg + 1];
            }
        }
        __syncthreads();

        // ---- stage x = [hL;hR] for 4 batches; prefetch lc/rc for gates ----
        float lcPre = 0.0f, rcPre = 0.0f;
        {
            for (int i = tid; i < 512; i += NT) {
                int m = i >> 7, dq = i & 127;
                int slot = (dq < 64) ? s_sL[m] : s_sR[m];
                *(float4*)&s_x[m * 1040 + dq * 4] =
                    __ldcg((const float4*)&g_states[((size_t)(b0 + m) * ROWS + slot) * DD + HH + (dq & 63) * 4]);
            }
            if (tid < 128) {    // prefetch c-halves needed by gates (hidden under GEMM)
                const int m = tid >> 5, u = r * 32 + (tid & 31);
                size_t rb = (size_t)(b0 + m) * ROWS;
                lcPre = __ldcg(&g_states[(rb + s_sL[m]) * DD + u]);
                rcPre = __ldcg(&g_states[(rb + s_sR[m]) * DD + u]);
            }
        }
        __syncthreads();

        // ---- compose GEMM, permuted cols: CTA r -> {g*256 + r*32 + lane} ----
        {
            const int d0 = wid * 64;
            const float* Wb = Wcomp + (size_t)d0 * FIVEH + r * 32 + lane;
            float ac[4][5];
#pragma unroll
            for (int m = 0; m < 4; m++)
#pragma unroll
                for (int j = 0; j < 5; j++) ac[m][j] = 0.0f;
#pragma unroll 4
            for (int d = 0; d < 64; d++) {
                const float* wr = Wb + (size_t)d * FIVEH;
                float w0 = wr[0], w1 = wr[256], w2 = wr[512], w3 = wr[768], w4 = wr[1024];
                float x0 = s_x[0 * 1040 + d0 + d];
                float x1 = s_x[1 * 1040 + d0 + d];
                float x2 = s_x[2 * 1040 + d0 + d];
                float x3 = s_x[3 * 1040 + d0 + d];
                ac[0][0] += x0 * w0; ac[0][1] += x0 * w1; ac[0][2] += x0 * w2; ac[0][3] += x0 * w3; ac[0][4] += x0 * w4;
                ac[1][0] += x1 * w0; ac[1][1] += x1 * w1; ac[1][2] += x1 * w2; ac[1][3] += x1 * w3; ac[1][4] += x1 * w4;
                ac[2][0] += x2 * w0; ac[2][1] += x2 * w1; ac[2][2] += x2 * w2; ac[2][3] += x2 * w3; ac[2][4] += x2 * w4;
                ac[3][0] += x3 * w0; ac[3][1] += x3 * w1; ac[3][2] += x3 * w2; ac[3][3] += x3 * w3; ac[3][4] += x3 * w4;
            }
#pragma unroll
            for (int m = 0; m < 4; m++)
#pragma unroll
                for (int j = 0; j < 5; j++)
                    s_part[(wid * 4 + m) * 160 + j * 32 + lane] = ac[m][j];
        }
        __syncthreads();

        // ---- combine + gates (CTA-local) + DSMEM h-broadcast ----
        const int R = SS + t;
        if (tid < 128) {
            const int m = tid >> 5, u32 = tid & 31;
            const int u = r * 32 + u32;
            float val[5];
#pragma unroll
            for (int g = 0; g < 5; g++) {
                float s = bcomp[g * 256 + u];
#pragma unroll
                for (int ks = 0; ks < 8; ks++)
                    s += s_part[(ks * 4 + m) * 160 + g * 32 + u32];
                val[g] = s;
            }
            const int b = b0 + m;
            size_t rb = (size_t)b * ROWS;
            float c = fsigm(val[1]) * lcPre + fsigm(val[2]) * rcPre + fsigm(val[0]) * ftanh(val[4]);
            float h = fsigm(val[3]) * ftanh(c);
            g_states[(rb + R) * DD + u] = c;
            g_states[(rb + R) * DD + HH + u] = h;
            uint32_t ha = (uint32_t)__cvta_generic_to_shared(&s_hf[m * 256 + u]);
#pragma unroll
            for (int pr = 0; pr < CL; pr++) dsmem_st(ha, pr, h);
        }
        CLUSTER_SYNC();   // h row R complete in every CTA's s_hf

        // ---- P proj from local s_hf (all smem) ----
        if (tid < 128) {
            const int k32 = tid & 31, m = tid >> 5;
            const float* hb = s_hf + m * 256;
            float acc = 0.0f;
#pragma unroll 8
            for (int d = 0; d < 256; d++) acc += hb[d] * s_ws[d * 32 + k32];
            g_P[((size_t)(b0 + m) * ROWS + R) * 256 + r * 32 + k32] = acc;
        }
        CLUSTER_SYNC();
    }

    // ================= MLP (root = row 190) =================
    for (int i = tid; i < 256; i += NT) {
        int m = i >> 6, dq = i & 63;
        *(float4*)&s_hf[m * 256 + dq * 4] =
            __ldcg((const float4*)&g_states[((size_t)(b0 + m) * ROWS + 190) * DD + HH + dq * 4]);
    }
    __syncthreads();
    {   // layer 1: per CTA 4 batches x 128 cols (of 1024)
        const int m = tid >> 6, cc = tid & 63;
        const int col = r * 128 + cc;
        float a0 = 0, a1 = 0;
        const float* hb = s_hf + m * 256;
#pragma unroll 4
        for (int d = 0; d < 256; d++) {
            float hv = hb[d];
            a0 += hv * Wm1[(size_t)d * MLPD + col];
            a1 += hv * Wm1[(size_t)d * MLPD + col + 64];
        }
        g_x1[(b0 + m) * MLPD + col]      = fmaxf(a0 + bm1[col], 0.0f);
        g_x1[(b0 + m) * MLPD + col + 64] = fmaxf(a1 + bm1[col + 64], 0.0f);
    }
    CLUSTER_SYNC();
    for (int i = tid; i < 1024; i += NT) {
        int m = i >> 8, k4 = i & 255;
        *(float4*)&s_x[m * 1040 + k4 * 4] = __ldcg((const float4*)&g_x1[(b0 + m) * MLPD + k4 * 4]);
    }
    __syncthreads();
    {   // layer 2: per CTA 4 batches x 128 cols, K=1024
        const int m = tid >> 6, cc = tid & 63;
        const int col = r * 128 + cc;
        float a0 = 0, a1 = 0;
        const float* xb = s_x + m * 1040;
#pragma unroll 4
        for (int k = 0; k < MLPD; k++) {
            float xv = xb[k];
            a0 += xv * Wm2[(size_t)k * MLPD + col];
            a1 += xv * Wm2[(size_t)k * MLPD + col + 64];
        }
        g_x2[(b0 + m) * MLPD + col]      = fmaxf(a0 + bm2[col], 0.0f);
        g_x2[(b0 + m) * MLPD + col + 64] = fmaxf(a1 + bm2[col + 64], 0.0f);
    }
    CLUSTER_SYNC();
    if (r == 0) {   // layer 3: 4 batches x 3 outputs
        for (int i = tid; i < 1024; i += NT) {
            int m = i >> 8, k4 = i & 255;
            *(float4*)&s_x[m * 1040 + k4 * 4] = __ldcg((const float4*)&g_x2[(b0 + m) * MLPD + k4 * 4]);
        }
        __syncthreads();
        if (wid < 4) {
            const int b = b0 + wid;
            const float* xb = s_x + wid * 1040;
            float a0 = 0, a1 = 0, a2 = 0;
            for (int k = lane; k < MLPD; k += 32) {
                float xv = xb[k];
                a0 += xv * Wout[k * 3 + 0];
                a1 += xv * Wout[k * 3 + 1];
                a2 += xv * Wout[k * 3 + 2];
            }
            for (int o = 16; o; o >>= 1) {
                a0 += __shfl_down_sync(0xFFFFFFFFu, a0, o);
                a1 += __shfl_down_sync(0xFFFFFFFFu, a1, o);
                a2 += __shfl_down_sync(0xFFFFFFFFu, a2, o);
            }
            if (lane == 0) {
                out[b * 3 + 0] = a0 + bout[0];
                out[b * 3 + 1] = a1 + bout[1];
                out[b * 3 + 2] = a2 + bout[2];
            }
        }
    }
}

// ---------------------------------------------------------------------------
extern "C" void kernel_launch(void* const* d_in, const int* in_sizes, int n_in,
                              void* d_out, int out_size)
{
    const int*   sent  = (const int*)d_in[0];
    const float* emb   = (const float*)d_in[2];
    const float* Wenc  = (const float*)d_in[3];
    const float* benc  = (const float*)d_in[4];
    const float* Wcomp = (const float*)d_in[5];
    const float* bcomp = (const float*)d_in[6];
    const float* Wsel1 = (const float*)d_in[7];
    const float* bsel1 = (const float*)d_in[8];
    const float* Wsel2 = (const float*)d_in[9];
    const float* bsel2 = (const float*)d_in[10];
    const float* Wm1   = (const float*)d_in[11];
    const float* bm1   = (const float*)d_in[12];
    const float* Wm2   = (const float*)d_in[13];
    const float* bm2   = (const float*)d_in[14];
    const float* Wout  = (const float*)d_in[15];
    const float* bout  = (const float*)d_in[16];
    float* out = (float*)d_out;

    // floats: 4160+8192+5120+1024+768 = 19264 ; ints: 768+8
    const int smem_scan = 19264 * 4 + 776 * 4;
    cudaFuncSetAttribute(scan_kernel, cudaFuncAttributeMaxDynamicSharedMemorySize, smem_scan);

    encode_kernel<<<dim3(8, 96), 256>>>(sent, emb, Wenc, benc);
    scan_kernel<<<NCTA, NT, smem_scan>>>(Wcomp, bcomp, Wsel1, bsel1, Wsel2, bsel2,
                                         Wm1, bm1, Wm2, bm2, Wout, bout, out);
}

// round 14
// speedup vs baseline: 1.7288x; 1.1158x over previous
#include <cuda_runtime.h>
#include <math.h>
#include <stdint.h>

#define BB    64
#define SS    96
#define EE    300
#define DD    512
#define HH    256
#define MLPD  1024
#define FIVEH 1280
#define ROWS  191     // 96 leaves + 95 merge rows; root = row 190
#define NCTA  128
#define CL    8       // cluster size; 16 clusters x 4 batches
#define NT    256

__device__ float g_states[BB * ROWS * DD];
__device__ float g_P[BB * ROWS * 256];     // selector projections [L(128)|R(128)]
__device__ float g_x1[BB * MLPD];
__device__ float g_x2[BB * MLPD];

#define CLUSTER_SYNC() do { \
    asm volatile("barrier.cluster.arrive.aligned;" ::: "memory"); \
    asm volatile("barrier.cluster.wait.aligned;" ::: "memory"); \
} while (0)

__device__ __forceinline__ float fsigm(float x) {
    return __fdividef(1.0f, 1.0f + __expf(-x));
}
__device__ __forceinline__ float ftanh(float x) {
    float cx = fminf(fmaxf(x, -15.0f), 15.0f);
    float e = __expf(2.0f * cx);
    return __fdividef(e - 1.0f, e + 1.0f);
}

// store float to the same smem offset in a peer CTA of the cluster
__device__ __forceinline__ void dsmem_st(uint32_t local_addr, int peer, float v) {
    uint32_t ra;
    asm volatile("mapa.shared::cluster.u32 %0, %1, %2;" : "=r"(ra) : "r"(local_addr), "r"(peer));
    asm volatile("st.shared::cluster.f32 [%0], %1;" :: "r"(ra), "f"(v) : "memory");
}

// ---------------------------------------------------------------------------
// encode: states[b][s][:] = embed[sent[b,s]] @ W_enc + b_enc   (rows 0..95)
// ---------------------------------------------------------------------------
__global__ __launch_bounds__(256) void encode_kernel(
    const int* __restrict__ sent, const float* __restrict__ emb,
    const float* __restrict__ Wenc, const float* __restrict__ benc)
{
    __shared__ float As[64 * 20];
    __shared__ float Bs[20 * 64];
    __shared__ int words[64];
    const int cb = blockIdx.x, tb = blockIdx.y, tid = threadIdx.x;
    const int tokenbase = tb * 64, colbase = cb * 64;
    if (tid < 64) words[tid] = sent[tokenbase + tid];
    __syncthreads();
    const int tx = tid & 15, ty = tid >> 4;
    float acc[4][4];
#pragma unroll
    for (int i = 0; i < 4; i++)
#pragma unroll
        for (int j = 0; j < 4; j++) acc[i][j] = 0.0f;
    for (int kb = 0; kb < EE; kb += 20) {
#pragma unroll
        for (int i = 0; i < 5; i++) {
            int e = tid + 256 * i, r = e / 20, k = e % 20;
            As[e] = emb[(size_t)words[r] * EE + kb + k];
        }
#pragma unroll
        for (int i = 0; i < 5; i++) {
            int e = tid + 256 * i, k = e >> 6, c = e & 63;
            Bs[e] = Wenc[(size_t)(kb + k) * DD + colbase + c];
        }
        __syncthreads();
#pragma unroll
        for (int k = 0; k < 20; k++) {
            float a0 = As[(4 * ty + 0) * 20 + k], a1 = As[(4 * ty + 1) * 20 + k];
            float a2 = As[(4 * ty + 2) * 20 + k], a3 = As[(4 * ty + 3) * 20 + k];
            float b0 = Bs[k * 64 + 4 * tx + 0], b1 = Bs[k * 64 + 4 * tx + 1];
            float b2 = Bs[k * 64 + 4 * tx + 2], b3 = Bs[k * 64 + 4 * tx + 3];
            acc[0][0] += a0 * b0; acc[0][1] += a0 * b1; acc[0][2] += a0 * b2; acc[0][3] += a0 * b3;
            acc[1][0] += a1 * b0; acc[1][1] += a1 * b1; acc[1][2] += a1 * b2; acc[1][3] += a1 * b3;
            acc[2][0] += a2 * b0; acc[2][1] += a2 * b1; acc[2][2] += a2 * b2; acc[2][3] += a2 * b3;
            acc[3][0] += a3 * b0; acc[3][1] += a3 * b1; acc[3][2] += a3 * b2; acc[3][3] += a3 * b3;
        }
        __syncthreads();
    }
#pragma unroll
    for (int i = 0; i < 4; i++) {
        int tok = tokenbase + 4 * ty + i;
        int b = tok / SS, s = tok - b * SS;
        int col = colbase + 4 * tx;
        float4 bia = *(const float4*)(benc + col);
        float4 v;
        v.x = acc[i][0] + bia.x; v.y = acc[i][1] + bia.y;
        v.z = acc[i][2] + bia.z; v.w = acc[i][3] + bia.w;
        *(float4*)(g_states + ((size_t)b * ROWS + s) * DD + col) = v;
    }
}

// ---------------------------------------------------------------------------
// persistent scan: 16 clusters of 8 CTAs; cluster -> 4 batches; 256 thr/CTA.
// CTA rank r: gates for unit stripe [r*32,+32) (permuted Wcomp cols);
// h AND affected-pair logit partials exchanged via DSMEM broadcast.
// ---------------------------------------------------------------------------
__global__ __launch_bounds__(NT, 1) __cluster_dims__(CL, 1, 1)
void scan_kernel(
    const float* __restrict__ Wcomp, const float* __restrict__ bcomp,
    const float* __restrict__ Wsel1, const float* __restrict__ bsel1,
    const float* __restrict__ Wsel2, const float* __restrict__ bsel2,
    const float* __restrict__ Wm1, const float* __restrict__ bm1,
    const float* __restrict__ Wm2, const float* __restrict__ bm2,
    const float* __restrict__ Wout, const float* __restrict__ bout,
    float* __restrict__ out)
{
    extern __shared__ float sm[];
    float* s_x     = sm;                     // 4160 : x = [hL;hR] x 4 batches
    float* s_wsT   = s_x + 4160;             // 8320 : Wsel1 slice TRANSPOSED [k32][260]
    float* s_part  = s_wsT + 8320;           // 5120 : GEMM partials
    float* s_hf    = s_part + 5120;          // 1024 : full h row R, 4 batches
    float* s_logit = s_hf + 1024;            // 768  : ping-pong
    float* s_plog  = s_logit + 768;          // 32   : [side(2)][m(4)][src(4)]
    int*   s_ord   = (int*)(s_plog + 32);    // 768  : ping-pong
    int*   s_sL    = s_ord + 768;            // 4
    int*   s_sR    = s_sL + 4;               // 4

    const int tid  = threadIdx.x;
    const int r    = blockIdx.x & (CL - 1);      // cluster rank
    const int b0   = (blockIdx.x >> 3) * 4;      // first batch of cluster
    const int lane = tid & 31;
    const int wid  = tid >> 5;                   // 8 warps
    const float b2v = bsel2[0];

    const int kP  = r * 32 + lane;               // this CTA's P slice index
    const int lrP = kP >> 7;
    const int uP  = kP & 127;
    const int wmm = wid & 3;
    const int wdh = wid >> 2;

    // ---- persistent TRANSPOSED Wsel1 slice: s_wsT[k32*260 + d] ----
    for (int i = tid; i < 8192; i += NT) {
        int d = i >> 5, k32 = i & 31;
        s_wsT[k32 * 260 + d] = Wsel1[(size_t)((r >> 2) * 256 + d) * 128 + (r & 3) * 32 + k32];
    }

    // ================= P-init: leaf rows 0..95, 4 rows per pass ==============
    {
        const float* wcol = Wsel1 + (size_t)(lrP * 256 + wdh * 128) * 128 + uP;
        for (int s0 = 0; s0 < SS; s0 += 4) {
            for (int i = tid; i < 1024; i += NT) {
                int m = i >> 8, rem = i & 255, rr = rem >> 6, dq = rem & 63;
                *(float4*)&s_x[m * 1040 + rr * 260 + dq * 4] =
                    __ldcg((const float4*)&g_states[((size_t)(b0 + m) * ROWS + s0 + rr) * DD + HH + dq * 4]);
            }
            __syncthreads();
#pragma unroll
            for (int rr = 0; rr < 4; rr++) {
                const float* hb = s_x + wmm * 1040 + rr * 260 + wdh * 128;
                float acc = 0.0f;
#pragma unroll 8
                for (int d = 0; d < 128; d++) acc += hb[d] * wcol[(size_t)d * 128];
                s_part[(wmm * 4 + rr) * 64 + wdh * 32 + lane] = acc;
            }
            __syncthreads();
            for (int i = tid; i < 512; i += NT) {
                int slot = i >> 5, l2 = i & 31;
                int m = slot >> 2, rr = slot & 3;
                float v = s_part[slot * 64 + l2] + s_part[slot * 64 + 32 + l2];
                g_P[((size_t)(b0 + m) * ROWS + s0 + rr) * 256 + r * 32 + l2] = v;
            }
            __syncthreads();
        }
    }
    CLUSTER_SYNC();

    // ================= initial logits + ord (buffer 0) ========================
    for (int i = tid; i < 384; i += NT) s_ord[i] = i % SS;
    for (int i = tid; i < 4 * (SS - 1); i += NT) {
        int m = i / (SS - 1), j = i - m * (SS - 1);
        size_t pb = ((size_t)(b0 + m) * ROWS + j) * 256;
        float s = 0.0f;
#pragma unroll 4
        for (int u4 = 0; u4 < 32; u4++) {
            float4 pl = __ldcg((const float4*)&g_P[pb + u4 * 4]);
            float4 pr = __ldcg((const float4*)&g_P[pb + 256 + 128 + u4 * 4]);
            float4 bb = *(const float4*)&bsel1[u4 * 4];
            float4 ww = *(const float4*)&Wsel2[u4 * 4];
            s += ftanh(pl.x + pr.x + bb.x) * ww.x + ftanh(pl.y + pr.y + bb.y) * ww.y
               + ftanh(pl.z + pr.z + bb.z) * ww.z + ftanh(pl.w + pr.w + bb.w) * ww.w;
        }
        s_logit[m * SS + j] = s + b2v;
    }
    __syncthreads();

    int idxReg = -1;

    // ================= main loop =================
    for (int t = 0; t < SS - 1; t++) {
        const int npairs = SS - 1 - t;
        // ---- part 1: shift + partial-sum logit update + argmax (warps 0-3) ----
        if (wid < 4) {
            const int m = wid;
            const int co = (t & 1) * 384 + m * SS;
            if (t > 0) {
                const int po = ((t - 1) & 1) * 384 + m * SS;
                const int idx = idxReg;
                const int limO = SS - t - 1, limL = SS - t - 2;
                for (int j = lane; j <= limO; j += 32)
                    s_ord[co + j] = (j < idx) ? s_ord[po + j]
                                  : (j == idx ? SS + t - 1 : s_ord[po + j + 1]);
                for (int j = lane; j <= limL; j += 32)
                    s_logit[co + j] = (j < idx - 1) ? s_logit[po + j]
                                    : ((j > idx) ? s_logit[po + j + 1] : -1e30f);
                __syncwarp();
                if (lane == 0) {    // new logits = sums of DSMEM partials
                    if (idx >= 1)
                        s_logit[co + idx - 1] = b2v + s_plog[m * 4 + 0] + s_plog[m * 4 + 1]
                                              + s_plog[m * 4 + 2] + s_plog[m * 4 + 3];
                    if (idx <= limL)
                        s_logit[co + idx] = b2v + s_plog[16 + m * 4 + 0] + s_plog[16 + m * 4 + 1]
                                          + s_plog[16 + m * 4 + 2] + s_plog[16 + m * 4 + 3];
                }
                __syncwarp();
            }
            float bv = -1e30f; int bi = 1 << 30;
            for (int j = lane; j < npairs; j += 32) {
                float v = s_logit[co + j];
                if (v > bv) { bv = v; bi = j; }
            }
            for (int o = 16; o; o >>= 1) {
                float ov = __shfl_down_sync(0xFFFFFFFFu, bv, o);
                int   oi = __shfl_down_sync(0xFFFFFFFFu, bi, o);
                if (ov > bv || (ov == bv && oi < bi)) { bv = ov; bi = oi; }
            }
            idxReg = __shfl_sync(0xFFFFFFFFu, bi, 0);
            if (lane == 0) {
                s_sL[m] = s_ord[co + idxReg];
                s_sR[m] = s_ord[co + idxReg + 1];
            }
        }
        __syncthreads();

        // ---- stage x; prefetch lc/rc and the old-neighbor P value ----
        float lcPre = 0.0f, rcPre = 0.0f, oldP = 0.0f;
        {
            for (int i = tid; i < 512; i += NT) {
                int m = i >> 7, dq = i & 127;
                int slot = (dq < 64) ? s_sL[m] : s_sR[m];
                *(float4*)&s_x[m * 1040 + dq * 4] =
                    __ldcg((const float4*)&g_states[((size_t)(b0 + m) * ROWS + slot) * DD + HH + (dq & 63) * 4]);
            }
            if (tid < 128) {
                const int m = tid >> 5, u = r * 32 + (tid & 31);
                size_t rb = (size_t)(b0 + m) * ROWS;
                lcPre = __ldcg(&g_states[(rb + s_sL[m]) * DD + u]);
                rcPre = __ldcg(&g_states[(rb + s_sR[m]) * DD + u]);
                const int co2 = (t & 1) * 384 + m * SS;
                const int idx = idxReg;          // warp m holds batch m's idx
                int jl = (idx - 1 > 0) ? idx - 1 : 0;
                int jr = (idx + 2 < SS - t - 1) ? idx + 2 : SS - t - 1;
                int prow = (r < 4) ? s_ord[co2 + jr] : s_ord[co2 + jl];
                oldP = __ldcg(&g_P[(rb + prow) * 256 + kP + ((r < 4) ? 128 : -128)]);
            }
        }
        __syncthreads();

        // ---- compose GEMM, permuted cols: CTA r -> {g*256 + r*32 + lane} ----
        {
            const int d0 = wid * 64;
            const float* Wb = Wcomp + (size_t)d0 * FIVEH + r * 32 + lane;
            float ac[4][5];
#pragma unroll
            for (int m = 0; m < 4; m++)
#pragma unroll
                for (int j = 0; j < 5; j++) ac[m][j] = 0.0f;
#pragma unroll 8
            for (int d = 0; d < 64; d++) {
                const float* wr = Wb + (size_t)d * FIVEH;
                float w0 = wr[0], w1 = wr[256], w2 = wr[512], w3 = wr[768], w4 = wr[1024];
                float x0 = s_x[0 * 1040 + d0 + d];
                float x1 = s_x[1 * 1040 + d0 + d];
                float x2 = s_x[2 * 1040 + d0 + d];
                float x3 = s_x[3 * 1040 + d0 + d];
                ac[0][0] += x0 * w0; ac[0][1] += x0 * w1; ac[0][2] += x0 * w2; ac[0][3] += x0 * w3; ac[0][4] += x0 * w4;
                ac[1][0] += x1 * w0; ac[1][1] += x1 * w1; ac[1][2] += x1 * w2; ac[1][3] += x1 * w3; ac[1][4] += x1 * w4;
                ac[2][0] += x2 * w0; ac[2][1] += x2 * w1; ac[2][2] += x2 * w2; ac[2][3] += x2 * w3; ac[2][4] += x2 * w4;
                ac[3][0] += x3 * w0; ac[3][1] += x3 * w1; ac[3][2] += x3 * w2; ac[3][3] += x3 * w3; ac[3][4] += x3 * w4;
            }
#pragma unroll
            for (int m = 0; m < 4; m++)
#pragma unroll
                for (int j = 0; j < 5; j++)
                    s_part[(wid * 4 + m) * 160 + j * 32 + lane] = ac[m][j];
        }
        __syncthreads();

        // ---- combine + gates (CTA-local) + DSMEM h-broadcast ----
        const int R = SS + t;
        if (tid < 128) {
            const int m = tid >> 5, u32 = tid & 31;
            const int u = r * 32 + u32;
            float val[5];
#pragma unroll
            for (int g = 0; g < 5; g++) {
                float s = bcomp[g * 256 + u];
#pragma unroll
                for (int ks = 0; ks < 8; ks++)
                    s += s_part[(ks * 4 + m) * 160 + g * 32 + u32];
                val[g] = s;
            }
            const int b = b0 + m;
            size_t rb = (size_t)b * ROWS;
            float c = fsigm(val[1]) * lcPre + fsigm(val[2]) * rcPre + fsigm(val[0]) * ftanh(val[4]);
            float h = fsigm(val[3]) * ftanh(c);
            g_states[(rb + R) * DD + u] = c;
            g_states[(rb + R) * DD + HH + u] = h;
            uint32_t ha = (uint32_t)__cvta_generic_to_shared(&s_hf[m * 256 + u]);
#pragma unroll
            for (int pr = 0; pr < CL; pr++) dsmem_st(ha, pr, h);
        }
        CLUSTER_SYNC();   // h row R complete in every CTA's s_hf

        // ---- P proj (vectorized smem) + distributed pair-logit partials ----
        if (tid < 128) {
            const int k32 = lane, m = tid >> 5;
            const float4* wv = (const float4*)&s_wsT[k32 * 260];
            const float4* hv = (const float4*)&s_hf[m * 256];
            float acc = 0.0f;
#pragma unroll 8
            for (int d4 = 0; d4 < 64; d4++) {
                float4 w = wv[d4], h = hv[d4];
                acc += h.x * w.x + h.y * w.y + h.z * w.z + h.w * w.w;
            }
            g_P[((size_t)(b0 + m) * ROWS + R) * 256 + kP] = acc;
            // partial of the affected pair logit for this CTA's 32 units
            float v = ftanh(oldP + acc + bsel1[uP]) * Wsel2[uP];
#pragma unroll
            for (int o = 16; o; o >>= 1) v += __shfl_down_sync(0xFFFFFFFFu, v, o);
            if (lane == 0) {
                int side = (r >= 4) ? 0 : 1;   // 0 = left pair, 1 = right pair
                uint32_t pa = (uint32_t)__cvta_generic_to_shared(&s_plog[side * 16 + m * 4 + (r & 3)]);
#pragma unroll
                for (int pr = 0; pr < CL; pr++) dsmem_st(pa, pr, v);
            }
        }
        CLUSTER_SYNC();
    }

    // ================= MLP (root = row 190) =================
    for (int i = tid; i < 256; i += NT) {
        int m = i >> 6, dq = i & 63;
        *(float4*)&s_hf[m * 256 + dq * 4] =
            __ldcg((const float4*)&g_states[((size_t)(b0 + m) * ROWS + 190) * DD + HH + dq * 4]);
    }
    __syncthreads();
    {   // layer 1: per CTA 4 batches x 128 cols (of 1024)
        const int m = tid >> 6, cc = tid & 63;
        const int col = r * 128 + cc;
        float a0 = 0, a1 = 0;
        const float* hb = s_hf + m * 256;
#pragma unroll 4
        for (int d = 0; d < 256; d++) {
            float hv = hb[d];
            a0 += hv * Wm1[(size_t)d * MLPD + col];
            a1 += hv * Wm1[(size_t)d * MLPD + col + 64];
        }
        g_x1[(b0 + m) * MLPD + col]      = fmaxf(a0 + bm1[col], 0.0f);
        g_x1[(b0 + m) * MLPD + col + 64] = fmaxf(a1 + bm1[col + 64], 0.0f);
    }
    CLUSTER_SYNC();
    for (int i = tid; i < 1024; i += NT) {
        int m = i >> 8, k4 = i & 255;
        *(float4*)&s_x[m * 1040 + k4 * 4] = __ldcg((const float4*)&g_x1[(b0 + m) * MLPD + k4 * 4]);
    }
    __syncthreads();
    {   // layer 2: per CTA 4 batches x 128 cols, K=1024
        const int m = tid >> 6, cc = tid & 63;
        const int col = r * 128 + cc;
        float a0 = 0, a1 = 0;
        const float* xb = s_x + m * 1040;
#pragma unroll 4
        for (int k = 0; k < MLPD; k++) {
            float xv = xb[k];
            a0 += xv * Wm2[(size_t)k * MLPD + col];
            a1 += xv * Wm2[(size_t)k * MLPD + col + 64];
        }
        g_x2[(b0 + m) * MLPD + col]      = fmaxf(a0 + bm2[col], 0.0f);
        g_x2[(b0 + m) * MLPD + col + 64] = fmaxf(a1 + bm2[col + 64], 0.0f);
    }
    CLUSTER_SYNC();
    if (r == 0) {   // layer 3: 4 batches x 3 outputs
        for (int i = tid; i < 1024; i += NT) {
            int m = i >> 8, k4 = i & 255;
            *(float4*)&s_x[m * 1040 + k4 * 4] = __ldcg((const float4*)&g_x2[(b0 + m) * MLPD + k4 * 4]);
        }
        __syncthreads();
        if (wid < 4) {
            const int b = b0 + wid;
            const float* xb = s_x + wid * 1040;
            float a0 = 0, a1 = 0, a2 = 0;
            for (int k = lane; k < MLPD; k += 32) {
                float xv = xb[k];
                a0 += xv * Wout[k * 3 + 0];
                a1 += xv * Wout[k * 3 + 1];
                a2 += xv * Wout[k * 3 + 2];
            }
            for (int o = 16; o; o >>= 1) {
                a0 += __shfl_down_sync(0xFFFFFFFFu, a0, o);
                a1 += __shfl_down_sync(0xFFFFFFFFu, a1, o);
                a2 += __shfl_down_sync(0xFFFFFFFFu, a2, o);
            }
            if (lane == 0) {
                out[b * 3 + 0] = a0 + bout[0];
                out[b * 3 + 1] = a1 + bout[1];
                out[b * 3 + 2] = a2 + bout[2];
            }
        }
    }
}

// ---------------------------------------------------------------------------
extern "C" void kernel_launch(void* const* d_in, const int* in_sizes, int n_in,
                              void* d_out, int out_size)
{
    const int*   sent  = (const int*)d_in[0];
    const float* emb   = (const float*)d_in[2];
    const float* Wenc  = (const float*)d_in[3];
    const float* benc  = (const float*)d_in[4];
    const float* Wcomp = (const float*)d_in[5];
    const float* bcomp = (const float*)d_in[6];
    const float* Wsel1 = (const float*)d_in[7];
    const float* bsel1 = (const float*)d_in[8];
    const float* Wsel2 = (const float*)d_in[9];
    const float* bsel2 = (const float*)d_in[10];
    const float* Wm1   = (const float*)d_in[11];
    const float* bm1   = (const float*)d_in[12];
    const float* Wm2   = (const float*)d_in[13];
    const float* bm2   = (const float*)d_in[14];
    const float* Wout  = (const float*)d_in[15];
    const float* bout  = (const float*)d_in[16];
    float* out = (float*)d_out;

    // floats: 4160+8320+5120+1024+768+32 = 19424 ; ints: 768+8
    const int smem_scan = 19424 * 4 + 776 * 4;
    cudaFuncSetAttribute(scan_kernel, cudaFuncAttributeMaxDynamicSharedMemorySize, smem_scan);

    encode_kernel<<<dim3(8, 96), 256>>>(sent, emb, Wenc, benc);
    scan_kernel<<<NCTA, NT, smem_scan>>>(Wcomp, bcomp, Wsel1, bsel1, Wsel2, bsel2,
                                         Wm1, bm1, Wm2, bm2, Wout, bout, out);
}